// round 5
// baseline (speedup 1.0000x reference)
#include <cuda_runtime.h>
#include <cuda_bf16.h>
#include <math_constants.h>
#include <cstdint>

#define Bb  2
#define Ls  4096
#define Ds  512
#define Hh  8
#define HDs 64
#define FFs 2048
#define WIN 128

// ---------------- scratch (device globals: allocation-guard safe) ----------
__device__ float g_q  [Bb*Ls*Ds];
__device__ float g_k  [Bb*Ls*Ds];
__device__ float g_v  [Bb*Ls*Ds];
__device__ float g_att[Bb*Ls*Ds];
__device__ float g_prj[Bb*Ls*Ds];
__device__ float g_h  [Bb*Ls*Ds];
__device__ float g_ff1[Bb*Ls*FFs];
__device__ float g_ff2[Bb*Ls*Ds];

// ---------------- helpers ---------------------------------------------------
__device__ __forceinline__ void cp16(uint32_t dst_smem, const void* src) {
    asm volatile("cp.async.ca.shared.global [%0], [%1], 16;\n"
                 :: "r"(dst_smem), "l"(src));
}
#define CP_COMMIT() asm volatile("cp.async.commit_group;\n")
#define CP_WAIT(n)  asm volatile("cp.async.wait_group %0;\n" :: "n"(n))

// raw fp32 bits fed to tf32 mma (HW reads top 19 bits; CUTLASS fast path)
__device__ __forceinline__ void mma_tf32(float d[4],
    uint32_t a0, uint32_t a1, uint32_t a2, uint32_t a3,
    uint32_t b0, uint32_t b1)
{
    asm volatile(
        "mma.sync.aligned.m16n8k8.row.col.f32.tf32.tf32.f32 "
        "{%0,%1,%2,%3}, {%4,%5,%6,%7}, {%8,%9}, {%0,%1,%2,%3};\n"
        : "+f"(d[0]), "+f"(d[1]), "+f"(d[2]), "+f"(d[3])
        : "r"(a0), "r"(a1), "r"(a2), "r"(a3), "r"(b0), "r"(b1));
}

// ============ double-buffered cp.async tf32 GEMM ============================
// C[M,N] = A[M,K] @ W[K,N] + bias (optional relu)
// 256 threads, block tile 128x128x32, warp grid 2x4 (warp tile 64x32)
#define BM 128
#define BN 128
#define BK 32
#define ASTRIDE 36     // 4 mod 32  -> conflict-free A frags
#define BSTRIDE 136    // 8 mod 32  -> conflict-free B frags
#define ASZ (BM * ASTRIDE)
#define BSZ (BK * BSTRIDE)
#define STAGE (ASZ + BSZ)
#define GEMM_SMEM (2 * STAGE * 4)

__global__ __launch_bounds__(256)
void tgemm_pipe(const float* __restrict__ A, const float* __restrict__ W,
                const float* __restrict__ bias, float* __restrict__ C,
                int M, int N, int K, int relu)
{
    extern __shared__ uint32_t sh[];
    const uint32_t sbase = (uint32_t)__cvta_generic_to_shared(sh);

    const int tid  = threadIdx.x;
    const int lane = tid & 31;
    const int warp = tid >> 5;
    const int gid  = lane >> 2;
    const int tg   = lane & 3;
    const int wm   = (warp >> 2) * 64;      // 0 / 64
    const int wn   = (warp & 3) * 32;       // 0..96
    const int bm   = blockIdx.y * BM;
    const int bn   = blockIdx.x * BN;

    // cp.async source/dest bases
    const int ar = tid >> 3, ac = (tid & 7) * 4;      // A: 128 rows, 8 f4/row
    const int br = tid >> 5, bc = (tid & 31) * 4;     // B: 32 rows, 32 f4/row
    const float* gA = A + (size_t)(bm + ar) * K + ac;
    const float* gB = W + (size_t)br * N + bn + bc;
    const uint32_t dA = sbase + (ar * ASTRIDE + ac) * 4;
    const uint32_t dB = sbase + (ASZ + br * BSTRIDE + bc) * 4;

    float d[4][4][4];
#pragma unroll
    for (int i = 0; i < 4; i++)
#pragma unroll
        for (int j = 0; j < 4; j++)
#pragma unroll
            for (int c = 0; c < 4; c++) d[i][j][c] = 0.f;

    // prologue: stage 0
#pragma unroll
    for (int i = 0; i < 4; i++) {
        cp16(dA + i * (32 * ASTRIDE * 4), gA + (size_t)i * 32 * K);
        cp16(dB + i * (8 * BSTRIDE * 4),  gB + (size_t)i * 8 * N);
    }
    CP_COMMIT();

    int buf = 0;
    for (int k0 = 0; k0 < K; k0 += BK, buf ^= 1) {
        if (k0 + BK < K) {
            const uint32_t off = (buf ^ 1) * (STAGE * 4);
#pragma unroll
            for (int i = 0; i < 4; i++) {
                cp16(dA + off + i * (32 * ASTRIDE * 4), gA + (size_t)(k0 + BK) + (size_t)i * 32 * K);
                cp16(dB + off + i * (8 * BSTRIDE * 4),  gB + (size_t)(k0 + BK) * N + (size_t)i * 8 * N);
            }
            CP_COMMIT();
            CP_WAIT(1);
        } else {
            CP_WAIT(0);
        }
        __syncthreads();

        const uint32_t* pA = sh + buf * STAGE;
        const uint32_t* pB = sh + buf * STAGE + ASZ;
#pragma unroll
        for (int kk = 0; kk < BK; kk += 8) {
            uint32_t bf[4][2];
#pragma unroll
            for (int jn = 0; jn < 4; jn++) {
                bf[jn][0] = pB[(kk + tg)     * BSTRIDE + wn + jn * 8 + gid];
                bf[jn][1] = pB[(kk + tg + 4) * BSTRIDE + wn + jn * 8 + gid];
            }
#pragma unroll
            for (int im = 0; im < 4; im++) {
                const int mr = wm + im * 16 + gid;
                uint32_t a0 = pA[mr       * ASTRIDE + kk + tg];
                uint32_t a1 = pA[(mr + 8) * ASTRIDE + kk + tg];
                uint32_t a2 = pA[mr       * ASTRIDE + kk + tg + 4];
                uint32_t a3 = pA[(mr + 8) * ASTRIDE + kk + tg + 4];
#pragma unroll
                for (int jn = 0; jn < 4; jn++)
                    mma_tf32(d[im][jn], a0, a1, a2, a3, bf[jn][0], bf[jn][1]);
            }
        }
        __syncthreads();
    }

#pragma unroll
    for (int jn = 0; jn < 4; jn++) {
        const int col = bn + wn + jn * 8 + 2 * tg;
        float2 bv = *(const float2*)&bias[col];
#pragma unroll
        for (int im = 0; im < 4; im++) {
            const int row = bm + wm + im * 16 + gid;
            float2 r0, r1;
            r0.x = d[im][jn][0] + bv.x;  r0.y = d[im][jn][1] + bv.y;
            r1.x = d[im][jn][2] + bv.x;  r1.y = d[im][jn][3] + bv.y;
            if (relu) {
                r0.x = fmaxf(r0.x, 0.f); r0.y = fmaxf(r0.y, 0.f);
                r1.x = fmaxf(r1.x, 0.f); r1.y = fmaxf(r1.y, 0.f);
            }
            *(float2*)&C[(size_t)row       * N + col] = r0;
            *(float2*)&C[(size_t)(row + 8) * N + col] = r1;
        }
    }
}

// ============== banded attention on tensor cores (flash-style) ==============
#define PK_STRIDE 68
#define V_STRIDE  72
#define ATTN_SMEM ((2 * 64 * PK_STRIDE + 64 * V_STRIDE) * 4)

__global__ __launch_bounds__(128)
void attn_mma(const float* __restrict__ q, const float* __restrict__ k,
              const float* __restrict__ v, float* __restrict__ out)
{
    extern __shared__ uint32_t sm[];
    uint32_t (*Ps)[PK_STRIDE] = (uint32_t(*)[PK_STRIDE])sm;
    uint32_t (*Ks)[PK_STRIDE] = (uint32_t(*)[PK_STRIDE])(sm + 64 * PK_STRIDE);
    uint32_t (*Vs)[V_STRIDE]  = (uint32_t(*)[V_STRIDE]) (sm + 2 * 64 * PK_STRIDE);
    const uint32_t sbase = (uint32_t)__cvta_generic_to_shared(sm);
    const uint32_t Ks_off = 64 * PK_STRIDE * 4;
    const uint32_t Vs_off = 2 * 64 * PK_STRIDE * 4;

    const int bh   = blockIdx.y;
    const int b    = bh >> 3;
    const int h    = bh & 7;
    const int q0   = blockIdx.x * 64;
    const int tid  = threadIdx.x;
    const int lane = tid & 31;
    const int warp = tid >> 5;
    const int gid  = lane >> 2;
    const int tg   = lane & 3;
    const int wm   = warp * 16;

    const int sr = tid >> 4, sc = (tid & 15) * 4;   // staging: 8 rows/iter

    // ---- stage Q via cp.async (raw f32 bits; scale folded into S) ----
    {
        const float* gq = q + ((size_t)(b * Ls + q0 + sr)) * Ds + h * HDs + sc;
        const uint32_t dq = sbase + (sr * PK_STRIDE + sc) * 4;
#pragma unroll
        for (int i = 0; i < 8; i++)
            cp16(dq + i * (8 * PK_STRIDE * 4), gq + (size_t)i * 8 * Ds);
    }
    CP_COMMIT();
    CP_WAIT(0);
    __syncthreads();

    uint32_t qa[8][4];
#pragma unroll
    for (int ks8 = 0; ks8 < 8; ks8++) {
        qa[ks8][0] = Ps[wm + gid    ][ks8 * 8 + tg    ];
        qa[ks8][1] = Ps[wm + gid + 8][ks8 * 8 + tg    ];
        qa[ks8][2] = Ps[wm + gid    ][ks8 * 8 + tg + 4];
        qa[ks8][3] = Ps[wm + gid + 8][ks8 * 8 + tg + 4];
    }

    float o[8][4];
#pragma unroll
    for (int jn = 0; jn < 8; jn++)
#pragma unroll
        for (int c = 0; c < 4; c++) o[jn][c] = 0.f;
    float m0 = -1e30f, m1 = -1e30f, l0 = 0.f, l1 = 0.f;

    const int row0 = q0 + wm + gid;
    const int row1 = row0 + 8;
    const int kstart = max(0, q0 - WIN);
    const int kend   = min(Ls, q0 + 64 + WIN);

    for (int kt = kstart; kt < kend; kt += 64) {
        __syncthreads();   // previous iteration done reading Ks/Vs
        {
            const float* gk = k + ((size_t)(b * Ls + kt + sr)) * Ds + h * HDs + sc;
            const float* gv = v + ((size_t)(b * Ls + kt + sr)) * Ds + h * HDs + sc;
            const uint32_t dk = sbase + Ks_off + (sr * PK_STRIDE + sc) * 4;
            const uint32_t dv = sbase + Vs_off + (sr * V_STRIDE  + sc) * 4;
#pragma unroll
            for (int i = 0; i < 8; i++) {
                cp16(dk + i * (8 * PK_STRIDE * 4), gk + (size_t)i * 8 * Ds);
                cp16(dv + i * (8 * V_STRIDE  * 4), gv + (size_t)i * 8 * Ds);
            }
        }
        CP_COMMIT();
        CP_WAIT(0);
        __syncthreads();

        // ---- S = Q K^T ----
        float s[8][4];
#pragma unroll
        for (int jn = 0; jn < 8; jn++)
#pragma unroll
            for (int c = 0; c < 4; c++) s[jn][c] = 0.f;

#pragma unroll
        for (int ks8 = 0; ks8 < 8; ks8++) {
#pragma unroll
            for (int jn = 0; jn < 8; jn++) {
                uint32_t b0 = Ks[jn * 8 + gid][ks8 * 8 + tg    ];
                uint32_t b1 = Ks[jn * 8 + gid][ks8 * 8 + tg + 4];
                mma_tf32(s[jn], qa[ks8][0], qa[ks8][1], qa[ks8][2], qa[ks8][3], b0, b1);
            }
        }

        // ---- scale + band mask + row max ----
        float rmax0 = -1e30f, rmax1 = -1e30f;
#pragma unroll
        for (int jn = 0; jn < 8; jn++) {
            int cb = kt + jn * 8 + 2 * tg;
            s[jn][0] = (abs(cb     - row0) <= WIN) ? s[jn][0] * 0.125f : -1e30f;
            s[jn][1] = (abs(cb + 1 - row0) <= WIN) ? s[jn][1] * 0.125f : -1e30f;
            s[jn][2] = (abs(cb     - row1) <= WIN) ? s[jn][2] * 0.125f : -1e30f;
            s[jn][3] = (abs(cb + 1 - row1) <= WIN) ? s[jn][3] * 0.125f : -1e30f;
            rmax0 = fmaxf(rmax0, fmaxf(s[jn][0], s[jn][1]));
            rmax1 = fmaxf(rmax1, fmaxf(s[jn][2], s[jn][3]));
        }
        rmax0 = fmaxf(rmax0, __shfl_xor_sync(0xffffffffu, rmax0, 1));
        rmax0 = fmaxf(rmax0, __shfl_xor_sync(0xffffffffu, rmax0, 2));
        rmax1 = fmaxf(rmax1, __shfl_xor_sync(0xffffffffu, rmax1, 1));
        rmax1 = fmaxf(rmax1, __shfl_xor_sync(0xffffffffu, rmax1, 2));

        // ---- online softmax update ----
        float mn0 = fmaxf(m0, rmax0);
        float mn1 = fmaxf(m1, rmax1);
        float sc0 = __expf(m0 - mn0);
        float sc1 = __expf(m1 - mn1);
        m0 = mn0; m1 = mn1;
        l0 *= sc0; l1 *= sc1;
#pragma unroll
        for (int jn = 0; jn < 8; jn++) {
            o[jn][0] *= sc0; o[jn][1] *= sc0;
            o[jn][2] *= sc1; o[jn][3] *= sc1;
        }

        // ---- P = exp(S - m), accumulate l, write P (raw f32 bits) ----
#pragma unroll
        for (int jn = 0; jn < 8; jn++) {
            float p0 = __expf(s[jn][0] - m0);
            float p1 = __expf(s[jn][1] - m0);
            float p2 = __expf(s[jn][2] - m1);
            float p3 = __expf(s[jn][3] - m1);
            l0 += p0 + p1;
            l1 += p2 + p3;
            *(uint2*)&Ps[wm + gid    ][jn * 8 + 2 * tg] =
                make_uint2(__float_as_uint(p0), __float_as_uint(p1));
            *(uint2*)&Ps[wm + gid + 8][jn * 8 + 2 * tg] =
                make_uint2(__float_as_uint(p2), __float_as_uint(p3));
        }
        __syncwarp();   // warp reads only its own 16 P rows

        // ---- O += P V ----
#pragma unroll
        for (int ks8 = 0; ks8 < 8; ks8++) {
            uint32_t a0 = Ps[wm + gid    ][ks8 * 8 + tg    ];
            uint32_t a1 = Ps[wm + gid + 8][ks8 * 8 + tg    ];
            uint32_t a2 = Ps[wm + gid    ][ks8 * 8 + tg + 4];
            uint32_t a3 = Ps[wm + gid + 8][ks8 * 8 + tg + 4];
#pragma unroll
            for (int jn = 0; jn < 8; jn++) {
                uint32_t b0 = Vs[ks8 * 8 + tg    ][jn * 8 + gid];
                uint32_t b1 = Vs[ks8 * 8 + tg + 4][jn * 8 + gid];
                mma_tf32(o[jn], a0, a1, a2, a3, b0, b1);
            }
        }
    }

    // ---- finalize ----
    l0 += __shfl_xor_sync(0xffffffffu, l0, 1);
    l0 += __shfl_xor_sync(0xffffffffu, l0, 2);
    l1 += __shfl_xor_sync(0xffffffffu, l1, 1);
    l1 += __shfl_xor_sync(0xffffffffu, l1, 2);
    const float inv0 = 1.f / l0;
    const float inv1 = 1.f / l1;

    float* o0 = out + ((size_t)(b * Ls + row0)) * Ds + h * HDs;
    float* o1 = out + ((size_t)(b * Ls + row1)) * Ds + h * HDs;
#pragma unroll
    for (int jn = 0; jn < 8; jn++) {
        int c = jn * 8 + 2 * tg;
        *(float2*)&o0[c] = make_float2(o[jn][0] * inv0, o[jn][1] * inv0);
        *(float2*)&o1[c] = make_float2(o[jn][2] * inv1, o[jn][3] * inv1);
    }
}

// ---------------- residual + LayerNorm -------------------------------------
__global__ __launch_bounds__(128)
void add_ln(const float* __restrict__ x, const float* __restrict__ r,
            const float* __restrict__ g, const float* __restrict__ bta,
            float* __restrict__ out)
{
    const int row = blockIdx.x;
    const int tid = threadIdx.x;
    const float* xr = x + (size_t)row * Ds;
    const float* rr = r + (size_t)row * Ds;

    __shared__ float t[Ds];
    __shared__ float s1[4], s2[4];

    float s = 0.f, ss = 0.f;
#pragma unroll
    for (int i = 0; i < 4; i++) {
        int c = tid + i * 128;
        float u = xr[c] + rr[c];
        t[c] = u;
        s += u;
        ss = fmaf(u, u, ss);
    }
#pragma unroll
    for (int o = 16; o; o >>= 1) {
        s  += __shfl_xor_sync(0xffffffffu, s,  o);
        ss += __shfl_xor_sync(0xffffffffu, ss, o);
    }
    if ((tid & 31) == 0) { s1[tid >> 5] = s; s2[tid >> 5] = ss; }
    __syncthreads();
    float S  = s1[0] + s1[1] + s1[2] + s1[3];
    float SS = s2[0] + s2[1] + s2[2] + s2[3];
    float mu   = S * (1.f / Ds);
    float var  = SS * (1.f / Ds) - mu * mu;
    float rstd = rsqrtf(var + 1e-5f);
#pragma unroll
    for (int i = 0; i < 4; i++) {
        int c = tid + i * 128;
        out[(size_t)row * Ds + c] = (t[c] - mu) * rstd * g[c] + bta[c];
    }
}

// ---------------- launch ----------------------------------------------------
extern "C" void kernel_launch(void* const* d_in, const int* in_sizes, int n_in,
                              void* d_out, int out_size)
{
    const float* x    = (const float*)d_in[0];
    const float* Wq   = (const float*)d_in[1];
    const float* bq   = (const float*)d_in[2];
    const float* Wk   = (const float*)d_in[3];
    const float* bk   = (const float*)d_in[4];
    const float* Wv   = (const float*)d_in[5];
    const float* bv   = (const float*)d_in[6];
    const float* Wo   = (const float*)d_in[7];
    const float* bo   = (const float*)d_in[8];
    const float* ln1g = (const float*)d_in[9];
    const float* ln1b = (const float*)d_in[10];
    const float* W1   = (const float*)d_in[11];
    const float* b1   = (const float*)d_in[12];
    const float* W2   = (const float*)d_in[13];
    const float* b2   = (const float*)d_in[14];
    const float* ln2g = (const float*)d_in[15];
    const float* ln2b = (const float*)d_in[16];
    float* out = (float*)d_out;

    float *q, *k, *v, *att, *prj, *h, *ff1, *ff2;
    cudaGetSymbolAddress((void**)&q,   g_q);
    cudaGetSymbolAddress((void**)&k,   g_k);
    cudaGetSymbolAddress((void**)&v,   g_v);
    cudaGetSymbolAddress((void**)&att, g_att);
    cudaGetSymbolAddress((void**)&prj, g_prj);
    cudaGetSymbolAddress((void**)&h,   g_h);
    cudaGetSymbolAddress((void**)&ff1, g_ff1);
    cudaGetSymbolAddress((void**)&ff2, g_ff2);

    const int M = Bb * Ls;

    static int attr_done = 0;
    cudaFuncSetAttribute(tgemm_pipe, cudaFuncAttributeMaxDynamicSharedMemorySize, GEMM_SMEM);
    cudaFuncSetAttribute(attn_mma,  cudaFuncAttributeMaxDynamicSharedMemorySize, ATTN_SMEM);
    (void)attr_done;

    dim3 gD(Ds / BN, M / BM);     // 4 x 64
    dim3 gF(FFs / BN, M / BM);    // 16 x 64

    tgemm_pipe<<<gD, 256, GEMM_SMEM>>>(x, Wq, bq, q, M, Ds, Ds, 0);
    tgemm_pipe<<<gD, 256, GEMM_SMEM>>>(x, Wk, bk, k, M, Ds, Ds, 0);
    tgemm_pipe<<<gD, 256, GEMM_SMEM>>>(x, Wv, bv, v, M, Ds, Ds, 0);

    attn_mma<<<dim3(Ls / 64, Bb * Hh), 128, ATTN_SMEM>>>(q, k, v, att);

    tgemm_pipe<<<gD, 256, GEMM_SMEM>>>(att, Wo, bo, prj, M, Ds, Ds, 0);
    add_ln<<<M, 128>>>(x, prj, ln1g, ln1b, h);

    tgemm_pipe<<<gF, 256, GEMM_SMEM>>>(h, W1, b1, ff1, M, FFs, Ds, 1);
    tgemm_pipe<<<gD, 256, GEMM_SMEM>>>(ff1, W2, b2, ff2, M, Ds, FFs, 0);
    add_ln<<<M, 128>>>(h, ff2, ln2g, ln2b, out);
}

// round 7
// speedup vs baseline: 1.5580x; 1.5580x over previous
#include <cuda_runtime.h>
#include <cuda_fp16.h>
#include <cstdint>

#define Bb  2
#define Ls  4096
#define Ds  512
#define Hh  8
#define HDs 64
#define FFs 2048
#define WIN 128
#define Ms  (Bb*Ls)
#define QS  1536     // fused qkv row stride (q|k|v)

// ---------------- scratch (device globals: allocation-guard safe) ----------
__device__ __half g_xh  [Ms*Ds];
__device__ float  g_qkv [Ms*QS];
__device__ __half g_att [Ms*Ds];
__device__ float  g_prj [Ms*Ds];
__device__ float  g_h   [Ms*Ds];
__device__ __half g_hr  [Ms*Ds];
__device__ __half g_ff1 [Ms*FFs];
__device__ float  g_ff2 [Ms*Ds];
__device__ __half g_wqkvt[3*Ds*Ds];
__device__ __half g_wot [Ds*Ds];
__device__ __half g_w1t [Ds*FFs];
__device__ __half g_w2t [FFs*Ds];
__device__ float  g_bqkv[QS];

// ---------------- helpers ---------------------------------------------------
__device__ __forceinline__ void cp16(uint32_t dst_smem, const void* src) {
    asm volatile("cp.async.ca.shared.global [%0], [%1], 16;\n"
                 :: "r"(dst_smem), "l"(src));
}
#define CP_COMMIT() asm volatile("cp.async.commit_group;\n")
#define CP_WAIT(n)  asm volatile("cp.async.wait_group %0;\n" :: "n"(n))

__device__ __forceinline__ uint32_t f2tf(float x) {     // rna tf32 round
    uint32_t u;
    asm("cvt.rna.tf32.f32 %0, %1;" : "=r"(u) : "f"(x));
    return u;
}
__device__ __forceinline__ float rna(float x) { return __uint_as_float(f2tf(x)); }

// fp16 mma, fp32 accumulate
__device__ __forceinline__ void mma_f16(float d[4],
    uint32_t a0, uint32_t a1, uint32_t a2, uint32_t a3, uint32_t b0, uint32_t b1)
{
    asm volatile(
        "mma.sync.aligned.m16n8k16.row.col.f32.f16.f16.f32 "
        "{%0,%1,%2,%3}, {%4,%5,%6,%7}, {%8,%9}, {%0,%1,%2,%3};\n"
        : "+f"(d[0]), "+f"(d[1]), "+f"(d[2]), "+f"(d[3])
        : "r"(a0), "r"(a1), "r"(a2), "r"(a3), "r"(b0), "r"(b1));
}

// tf32 mma (attention)
__device__ __forceinline__ void mma_tf32(float d[4],
    uint32_t a0, uint32_t a1, uint32_t a2, uint32_t a3, uint32_t b0, uint32_t b1)
{
    asm volatile(
        "mma.sync.aligned.m16n8k8.row.col.f32.tf32.tf32.f32 "
        "{%0,%1,%2,%3}, {%4,%5,%6,%7}, {%8,%9}, {%0,%1,%2,%3};\n"
        : "+f"(d[0]), "+f"(d[1]), "+f"(d[2]), "+f"(d[3])
        : "r"(a0), "r"(a1), "r"(a2), "r"(a3), "r"(b0), "r"(b1));
}

// ================= prologue kernels =========================================
__global__ __launch_bounds__(256)
void to_half(const float* __restrict__ in, __half* __restrict__ o, int n4)
{
    int i = blockIdx.x * blockDim.x + threadIdx.x;
    if (i < n4) {
        float4 t = ((const float4*)in)[i];
        __half2 lo = __floats2half2_rn(t.x, t.y);
        __half2 hi = __floats2half2_rn(t.z, t.w);
        ((uint2*)o)[i] = make_uint2(*(uint32_t*)&lo, *(uint32_t*)&hi);
    }
}

// W[K][N] (fp32) -> Wt[N][K] (half)
__global__ __launch_bounds__(256)
void transpose_half(const float* __restrict__ W, __half* __restrict__ Wt, int K, int N)
{
    __shared__ float t[32][33];
    const int nx = blockIdx.x * 32, ky = blockIdx.y * 32;
    const int x = threadIdx.x, y = threadIdx.y;   // 32 x 8
#pragma unroll
    for (int j = 0; j < 32; j += 8)
        t[y + j][x] = W[(size_t)(ky + y + j) * N + nx + x];
    __syncthreads();
#pragma unroll
    for (int j = 0; j < 32; j += 8)
        Wt[(size_t)(nx + y + j) * K + ky + x] = __float2half(t[x][y + j]);
}

__global__ void concat3(const float* __restrict__ a, const float* __restrict__ b,
                        const float* __restrict__ c, float* __restrict__ o)
{
    int i = blockIdx.x * blockDim.x + threadIdx.x;   // 3 x 512
    o[i] = (i < Ds) ? a[i] : (i < 2 * Ds) ? b[i - Ds] : c[i - 2 * Ds];
}

// ================= fp16 tensor-core GEMM ====================================
// C[M,N] = A[M,K] @ Bt[N,K]^T + bias.  256 thr, tile 128x128x64, warps 2x4.
// out_mode: 0 = fp32, 1 = fp32 rna-rounded (tf32), 2 = half
#define HST    72                       // smem row stride in halves
#define HAS    (128 * HST)              // halves per A (or B) stage
#define HSTG   (2 * HAS)                // halves per stage (A+B)
#define HG_SMEM (2 * HSTG * 2)          // bytes, 2 stages

__global__ __launch_bounds__(256)
void hgemm(const __half* __restrict__ A, const __half* __restrict__ Bt,
           const float* __restrict__ bias, void* __restrict__ Cv,
           int M, int N, int K, int relu, int out_mode)
{
    extern __shared__ __align__(256) __half sh[];
    const uint32_t sb = (uint32_t)__cvta_generic_to_shared(sh);

    const int tid  = threadIdx.x;
    const int lane = tid & 31;
    const int warp = tid >> 5;
    const int gid  = lane >> 2;
    const int tg   = lane & 3;
    const int wm   = (warp >> 2) * 64;
    const int wn   = (warp & 3) * 32;
    const int bm   = blockIdx.y * 128;
    const int bn   = blockIdx.x * 128;

    const int ar = tid >> 3;            // 0..31
    const int ac = (tid & 7) * 8;       // half offset, 16B chunks

    float d[4][4][4];
#pragma unroll
    for (int i = 0; i < 4; i++)
#pragma unroll
        for (int j = 0; j < 4; j++)
#pragma unroll
            for (int c = 0; c < 4; c++) d[i][j][c] = 0.f;

    auto do_load = [&](int stage, int k0) {
        const __half* pa = A  + (size_t)(bm + ar) * K + k0 + ac;
        const __half* pb = Bt + (size_t)(bn + ar) * K + k0 + ac;
        const uint32_t ba = sb + (uint32_t)stage * (HSTG * 2);
        const uint32_t bb = ba + HAS * 2;
#pragma unroll
        for (int i = 0; i < 4; i++) {
            uint32_t off = (uint32_t)((ar + 32 * i) * HST + ac) * 2;
            cp16(ba + off, pa + (size_t)32 * i * K);
            cp16(bb + off, pb + (size_t)32 * i * K);
        }
    };

    const int T = K / 64;
    do_load(0, 0);
    CP_COMMIT();

    int buf = 0;
    for (int t = 0; t < T; t++, buf ^= 1) {
        if (t + 1 < T) {
            do_load(buf ^ 1, (t + 1) * 64);
            CP_COMMIT();
            CP_WAIT(1);
        } else {
            CP_WAIT(0);
        }
        __syncthreads();

        const __half* pA = sh + buf * HSTG;
        const __half* pB = pA + HAS;
#pragma unroll
        for (int kk = 0; kk < 64; kk += 16) {
            uint32_t bf[4][2];
#pragma unroll
            for (int jn = 0; jn < 4; jn++) {
                const __half* bp = &pB[(wn + jn * 8 + gid) * HST + kk + 2 * tg];
                bf[jn][0] = *(const uint32_t*)bp;
                bf[jn][1] = *(const uint32_t*)(bp + 8);
            }
#pragma unroll
            for (int im = 0; im < 4; im++) {
                const __half* ap = &pA[(wm + im * 16 + gid) * HST + kk + 2 * tg];
                uint32_t a0 = *(const uint32_t*)ap;
                uint32_t a1 = *(const uint32_t*)(ap + 8 * HST);
                uint32_t a2 = *(const uint32_t*)(ap + 8);
                uint32_t a3 = *(const uint32_t*)(ap + 8 * HST + 8);
#pragma unroll
                for (int jn = 0; jn < 4; jn++)
                    mma_f16(d[im][jn], a0, a1, a2, a3, bf[jn][0], bf[jn][1]);
            }
        }
        __syncthreads();
    }

    // epilogue
#pragma unroll
    for (int jn = 0; jn < 4; jn++) {
        const int col = bn + wn + jn * 8 + 2 * tg;
        float2 bv = *(const float2*)&bias[col];
#pragma unroll
        for (int im = 0; im < 4; im++) {
            const int row = bm + wm + im * 16 + gid;
            float v0 = d[im][jn][0] + bv.x, v1 = d[im][jn][1] + bv.y;
            float v2 = d[im][jn][2] + bv.x, v3 = d[im][jn][3] + bv.y;
            if (relu) {
                v0 = fmaxf(v0, 0.f); v1 = fmaxf(v1, 0.f);
                v2 = fmaxf(v2, 0.f); v3 = fmaxf(v3, 0.f);
            }
            if (out_mode == 2) {
                __half* Ch = (__half*)Cv;
                *(__half2*)&Ch[(size_t)row       * N + col] = __floats2half2_rn(v0, v1);
                *(__half2*)&Ch[(size_t)(row + 8) * N + col] = __floats2half2_rn(v2, v3);
            } else {
                if (out_mode == 1) { v0 = rna(v0); v1 = rna(v1); v2 = rna(v2); v3 = rna(v3); }
                float* Cf = (float*)Cv;
                *(float2*)&Cf[(size_t)row       * N + col] = make_float2(v0, v1);
                *(float2*)&Cf[(size_t)(row + 8) * N + col] = make_float2(v2, v3);
            }
        }
    }
}

// ============== banded attention on tensor cores (flash-style) ==============
#define PK_STRIDE 68
#define V_STRIDE  72
#define ATTN_SMEM ((2 * 64 * PK_STRIDE + 64 * V_STRIDE) * 4)

__global__ __launch_bounds__(128)
void attn_mma(const float* __restrict__ qkv, __half* __restrict__ out)
{
    extern __shared__ uint32_t sm[];
    uint32_t (*Ps)[PK_STRIDE] = (uint32_t(*)[PK_STRIDE])sm;
    uint32_t (*Ks)[PK_STRIDE] = (uint32_t(*)[PK_STRIDE])(sm + 64 * PK_STRIDE);
    uint32_t (*Vs)[V_STRIDE]  = (uint32_t(*)[V_STRIDE]) (sm + 2 * 64 * PK_STRIDE);
    const uint32_t sbase = (uint32_t)__cvta_generic_to_shared(sm);
    const uint32_t Ks_off = 64 * PK_STRIDE * 4;
    const uint32_t Vs_off = 2 * 64 * PK_STRIDE * 4;

    const int bh   = blockIdx.y;
    const int b    = bh >> 3;
    const int h    = bh & 7;
    const int q0   = blockIdx.x * 64;
    const int tid  = threadIdx.x;
    const int lane = tid & 31;
    const int warp = tid >> 5;
    const int gid  = lane >> 2;
    const int tg   = lane & 3;
    const int wm   = warp * 16;

    const int sr = tid >> 4, sc = (tid & 15) * 4;

    {
        const float* gq = qkv + ((size_t)(b * Ls + q0 + sr)) * QS + h * HDs + sc;
        const uint32_t dq = sbase + (sr * PK_STRIDE + sc) * 4;
#pragma unroll
        for (int i = 0; i < 8; i++)
            cp16(dq + i * (8 * PK_STRIDE * 4), gq + (size_t)i * 8 * QS);
    }
    CP_COMMIT();
    CP_WAIT(0);
    __syncthreads();

    uint32_t qa[8][4];
#pragma unroll
    for (int ks8 = 0; ks8 < 8; ks8++) {
        qa[ks8][0] = Ps[wm + gid    ][ks8 * 8 + tg    ];
        qa[ks8][1] = Ps[wm + gid + 8][ks8 * 8 + tg    ];
        qa[ks8][2] = Ps[wm + gid    ][ks8 * 8 + tg + 4];
        qa[ks8][3] = Ps[wm + gid + 8][ks8 * 8 + tg + 4];
    }

    float o[8][4];
#pragma unroll
    for (int jn = 0; jn < 8; jn++)
#pragma unroll
        for (int c = 0; c < 4; c++) o[jn][c] = 0.f;
    float m0 = -1e30f, m1 = -1e30f, l0 = 0.f, l1 = 0.f;

    const int row0 = q0 + wm + gid;
    const int row1 = row0 + 8;
    const int kstart = max(0, q0 - WIN);
    const int kend   = min(Ls, q0 + 64 + WIN);

    for (int kt = kstart; kt < kend; kt += 64) {
        __syncthreads();
        {
            const float* gk = qkv + ((size_t)(b * Ls + kt + sr)) * QS + Ds     + h * HDs + sc;
            const float* gv = qkv + ((size_t)(b * Ls + kt + sr)) * QS + 2 * Ds + h * HDs + sc;
            const uint32_t dk = sbase + Ks_off + (sr * PK_STRIDE + sc) * 4;
            const uint32_t dv = sbase + Vs_off + (sr * V_STRIDE  + sc) * 4;
#pragma unroll
            for (int i = 0; i < 8; i++) {
                cp16(dk + i * (8 * PK_STRIDE * 4), gk + (size_t)i * 8 * QS);
                cp16(dv + i * (8 * V_STRIDE  * 4), gv + (size_t)i * 8 * QS);
            }
        }
        CP_COMMIT();
        CP_WAIT(0);
        __syncthreads();

        float s[8][4];
#pragma unroll
        for (int jn = 0; jn < 8; jn++)
#pragma unroll
            for (int c = 0; c < 4; c++) s[jn][c] = 0.f;

#pragma unroll
        for (int ks8 = 0; ks8 < 8; ks8++) {
#pragma unroll
            for (int jn = 0; jn < 8; jn++) {
                uint32_t b0 = Ks[jn * 8 + gid][ks8 * 8 + tg    ];
                uint32_t b1 = Ks[jn * 8 + gid][ks8 * 8 + tg + 4];
                mma_tf32(s[jn], qa[ks8][0], qa[ks8][1], qa[ks8][2], qa[ks8][3], b0, b1);
            }
        }

        float rmax0 = -1e30f, rmax1 = -1e30f;
#pragma unroll
        for (int jn = 0; jn < 8; jn++) {
            int cb = kt + jn * 8 + 2 * tg;
            s[jn][0] = (abs(cb     - row0) <= WIN) ? s[jn][0] * 0.125f : -1e30f;
            s[jn][1] = (abs(cb + 1 - row0) <= WIN) ? s[jn][1] * 0.125f : -1e30f;
            s[jn][2] = (abs(cb     - row1) <= WIN) ? s[jn][2] * 0.125f : -1e30f;
            s[jn][3] = (abs(cb + 1 - row1) <= WIN) ? s[jn][3] * 0.125f : -1e30f;
            rmax0 = fmaxf(rmax0, fmaxf(s[jn][0], s[jn][1]));
            rmax1 = fmaxf(rmax1, fmaxf(s[jn][2], s[jn][3]));
        }
        rmax0 = fmaxf(rmax0, __shfl_xor_sync(0xffffffffu, rmax0, 1));
        rmax0 = fmaxf(rmax0, __shfl_xor_sync(0xffffffffu, rmax0, 2));
        rmax1 = fmaxf(rmax1, __shfl_xor_sync(0xffffffffu, rmax1, 1));
        rmax1 = fmaxf(rmax1, __shfl_xor_sync(0xffffffffu, rmax1, 2));

        float mn0 = fmaxf(m0, rmax0);
        float mn1 = fmaxf(m1, rmax1);
        float sc0 = __expf(m0 - mn0);
        float sc1 = __expf(m1 - mn1);
        m0 = mn0; m1 = mn1;
        l0 *= sc0; l1 *= sc1;
#pragma unroll
        for (int jn = 0; jn < 8; jn++) {
            o[jn][0] *= sc0; o[jn][1] *= sc0;
            o[jn][2] *= sc1; o[jn][3] *= sc1;
        }

#pragma unroll
        for (int jn = 0; jn < 8; jn++) {
            float p0 = __expf(s[jn][0] - m0);
            float p1 = __expf(s[jn][1] - m0);
            float p2 = __expf(s[jn][2] - m1);
            float p3 = __expf(s[jn][3] - m1);
            l0 += p0 + p1;
            l1 += p2 + p3;
            *(uint2*)&Ps[wm + gid    ][jn * 8 + 2 * tg] = make_uint2(f2tf(p0), f2tf(p1));
            *(uint2*)&Ps[wm + gid + 8][jn * 8 + 2 * tg] = make_uint2(f2tf(p2), f2tf(p3));
        }
        __syncwarp();

#pragma unroll
        for (int ks8 = 0; ks8 < 8; ks8++) {
            uint32_t a0 = Ps[wm + gid    ][ks8 * 8 + tg    ];
            uint32_t a1 = Ps[wm + gid + 8][ks8 * 8 + tg    ];
            uint32_t a2 = Ps[wm + gid    ][ks8 * 8 + tg + 4];
            uint32_t a3 = Ps[wm + gid + 8][ks8 * 8 + tg + 4];
#pragma unroll
            for (int jn = 0; jn < 8; jn++) {
                uint32_t b0 = Vs[ks8 * 8 + tg    ][jn * 8 + gid];
                uint32_t b1 = Vs[ks8 * 8 + tg + 4][jn * 8 + gid];
                mma_tf32(o[jn], a0, a1, a2, a3, b0, b1);
            }
        }
    }

    l0 += __shfl_xor_sync(0xffffffffu, l0, 1);
    l0 += __shfl_xor_sync(0xffffffffu, l0, 2);
    l1 += __shfl_xor_sync(0xffffffffu, l1, 1);
    l1 += __shfl_xor_sync(0xffffffffu, l1, 2);
    const float inv0 = 1.f / l0;
    const float inv1 = 1.f / l1;

    __half* o0 = out + ((size_t)(b * Ls + row0)) * Ds + h * HDs;
    __half* o1 = out + ((size_t)(b * Ls + row1)) * Ds + h * HDs;
#pragma unroll
    for (int jn = 0; jn < 8; jn++) {
        int c = jn * 8 + 2 * tg;
        *(__half2*)&o0[c] = __floats2half2_rn(o[jn][0] * inv0, o[jn][1] * inv0);
        *(__half2*)&o1[c] = __floats2half2_rn(o[jn][2] * inv1, o[jn][3] * inv1);
    }
}

// ---------------- residual + LayerNorm (optional half twin) -----------------
__global__ __launch_bounds__(128)
void add_ln(const float* __restrict__ x, const float* __restrict__ r,
            const float* __restrict__ g, const float* __restrict__ bta,
            float* __restrict__ out, __half* __restrict__ out_r)
{
    const int row = blockIdx.x;
    const int tid = threadIdx.x;
    const float* xr = x + (size_t)row * Ds;
    const float* rr = r + (size_t)row * Ds;

    __shared__ float t[Ds];
    __shared__ float s1[4], s2[4];

    float s = 0.f, ss = 0.f;
#pragma unroll
    for (int i = 0; i < 4; i++) {
        int c = tid + i * 128;
        float u = xr[c] + rr[c];
        t[c] = u;
        s += u;
        ss = fmaf(u, u, ss);
    }
#pragma unroll
    for (int o = 16; o; o >>= 1) {
        s  += __shfl_xor_sync(0xffffffffu, s,  o);
        ss += __shfl_xor_sync(0xffffffffu, ss, o);
    }
    if ((tid & 31) == 0) { s1[tid >> 5] = s; s2[tid >> 5] = ss; }
    __syncthreads();
    float S  = s1[0] + s1[1] + s1[2] + s1[3];
    float SS = s2[0] + s2[1] + s2[2] + s2[3];
    float mu   = S * (1.f / Ds);
    float var  = SS * (1.f / Ds) - mu * mu;
    float rstd = rsqrtf(var + 1e-5f);
#pragma unroll
    for (int i = 0; i < 4; i++) {
        int c = tid + i * 128;
        float val = (t[c] - mu) * rstd * g[c] + bta[c];
        out[(size_t)row * Ds + c] = val;
        if (out_r) out_r[(size_t)row * Ds + c] = __float2half(val);
    }
}

// ---------------- launch ----------------------------------------------------
extern "C" void kernel_launch(void* const* d_in, const int* in_sizes, int n_in,
                              void* d_out, int out_size)
{
    const float* x    = (const float*)d_in[0];
    const float* Wq   = (const float*)d_in[1];
    const float* bq   = (const float*)d_in[2];
    const float* Wk   = (const float*)d_in[3];
    const float* bk   = (const float*)d_in[4];
    const float* Wv   = (const float*)d_in[5];
    const float* bv   = (const float*)d_in[6];
    const float* Wo   = (const float*)d_in[7];
    const float* bo   = (const float*)d_in[8];
    const float* ln1g = (const float*)d_in[9];
    const float* ln1b = (const float*)d_in[10];
    const float* W1   = (const float*)d_in[11];
    const float* b1   = (const float*)d_in[12];
    const float* W2   = (const float*)d_in[13];
    const float* b2   = (const float*)d_in[14];
    const float* ln2g = (const float*)d_in[15];
    const float* ln2b = (const float*)d_in[16];
    float* out = (float*)d_out;

    __half *xh, *att, *hr, *ff1, *wqkvt, *wot, *w1t, *w2t;
    float  *qkv, *prj, *h, *ff2, *bqkv;
    cudaGetSymbolAddress((void**)&xh,    g_xh);
    cudaGetSymbolAddress((void**)&qkv,   g_qkv);
    cudaGetSymbolAddress((void**)&att,   g_att);
    cudaGetSymbolAddress((void**)&prj,   g_prj);
    cudaGetSymbolAddress((void**)&h,     g_h);
    cudaGetSymbolAddress((void**)&hr,    g_hr);
    cudaGetSymbolAddress((void**)&ff1,   g_ff1);
    cudaGetSymbolAddress((void**)&ff2,   g_ff2);
    cudaGetSymbolAddress((void**)&wqkvt, g_wqkvt);
    cudaGetSymbolAddress((void**)&wot,   g_wot);
    cudaGetSymbolAddress((void**)&w1t,   g_w1t);
    cudaGetSymbolAddress((void**)&w2t,   g_w2t);
    cudaGetSymbolAddress((void**)&bqkv,  g_bqkv);

    cudaFuncSetAttribute(hgemm,    cudaFuncAttributeMaxDynamicSharedMemorySize, HG_SMEM);
    cudaFuncSetAttribute(attn_mma, cudaFuncAttributeMaxDynamicSharedMemorySize, ATTN_SMEM);

    dim3 tb(32, 8);

    // prologue: convert x, transpose weights to half [N][K]
    to_half<<<(Ms * Ds / 4 + 255) / 256, 256>>>(x, xh, Ms * Ds / 4);
    transpose_half<<<dim3(Ds / 32, Ds / 32), tb>>>(Wq, wqkvt,                 Ds, Ds);
    transpose_half<<<dim3(Ds / 32, Ds / 32), tb>>>(Wk, wqkvt + Ds * Ds,       Ds, Ds);
    transpose_half<<<dim3(Ds / 32, Ds / 32), tb>>>(Wv, wqkvt + 2 * Ds * Ds,   Ds, Ds);
    transpose_half<<<dim3(Ds / 32, Ds / 32), tb>>>(Wo, wot, Ds, Ds);
    transpose_half<<<dim3(FFs / 32, Ds / 32), tb>>>(W1, w1t, Ds, FFs);
    transpose_half<<<dim3(Ds / 32, FFs / 32), tb>>>(W2, w2t, FFs, Ds);
    concat3<<<3, 512>>>(bq, bk, bv, bqkv);

    // fused QKV: [Ms, 1536] = xh @ WqkvT^T, outputs rna-rounded fp32
    hgemm<<<dim3(QS / 128, Ms / 128), 256, HG_SMEM>>>(xh, wqkvt, bqkv, qkv,
                                                      Ms, QS, Ds, 0, 1);

    attn_mma<<<dim3(Ls / 64, Bb * Hh), 128, ATTN_SMEM>>>(qkv, att);

    hgemm<<<dim3(Ds / 128, Ms / 128), 256, HG_SMEM>>>(att, wot, bo, prj,
                                                      Ms, Ds, Ds, 0, 0);
    add_ln<<<Ms, 128>>>(x, prj, ln1g, ln1b, h, hr);

    hgemm<<<dim3(FFs / 128, Ms / 128), 256, HG_SMEM>>>(hr, w1t, b1, ff1,
                                                       Ms, FFs, Ds, 1, 2);
    hgemm<<<dim3(Ds / 128, Ms / 128), 256, HG_SMEM>>>(ff1, w2t, b2, ff2,
                                                      Ms, Ds, FFs, 0, 0);
    add_ln<<<Ms, 128>>>(h, ff2, ln2g, ln2b, out, nullptr);
}

// round 8
// speedup vs baseline: 1.7316x; 1.1114x over previous
#include <cuda_runtime.h>
#include <cuda_fp16.h>
#include <cstdint>

#define Bb  2
#define Ls  4096
#define Ds  512
#define Hh  8
#define HDs 64
#define FFs 2048
#define WIN 128
#define Ms  (Bb*Ls)
#define QS  1536     // fused qkv row stride (q|k|v) in halves

// ---------------- scratch (device globals: allocation-guard safe) ----------
__device__ __half g_xh  [Ms*Ds];
__device__ __half g_qkv [Ms*QS];
__device__ __half g_att [Ms*Ds];
__device__ float  g_prj [Ms*Ds];
__device__ float  g_h   [Ms*Ds];
__device__ __half g_hr  [Ms*Ds];
__device__ __half g_ff1 [Ms*FFs];
__device__ float  g_ff2 [Ms*Ds];
__device__ __half g_wqkvt[3*Ds*Ds];
__device__ __half g_wot [Ds*Ds];
__device__ __half g_w1t [Ds*FFs];
__device__ __half g_w2t [FFs*Ds];
__device__ float  g_bqkv[QS];

// ---------------- helpers ---------------------------------------------------
__device__ __forceinline__ void cp16(uint32_t dst_smem, const void* src) {
    asm volatile("cp.async.ca.shared.global [%0], [%1], 16;\n"
                 :: "r"(dst_smem), "l"(src));
}
#define CP_COMMIT() asm volatile("cp.async.commit_group;\n")
#define CP_WAIT(n)  asm volatile("cp.async.wait_group %0;\n" :: "n"(n))

__device__ __forceinline__ uint32_t f2tf(float x) {
    uint32_t u;
    asm("cvt.rna.tf32.f32 %0, %1;" : "=r"(u) : "f"(x));
    return u;
}
__device__ __forceinline__ float rna(float x) { return __uint_as_float(f2tf(x)); }

// fp16 mma, fp32 accumulate
__device__ __forceinline__ void mma_f16(float d[4],
    uint32_t a0, uint32_t a1, uint32_t a2, uint32_t a3, uint32_t b0, uint32_t b1)
{
    asm volatile(
        "mma.sync.aligned.m16n8k16.row.col.f32.f16.f16.f32 "
        "{%0,%1,%2,%3}, {%4,%5,%6,%7}, {%8,%9}, {%0,%1,%2,%3};\n"
        : "+f"(d[0]), "+f"(d[1]), "+f"(d[2]), "+f"(d[3])
        : "r"(a0), "r"(a1), "r"(a2), "r"(a3), "r"(b0), "r"(b1));
}

__device__ __forceinline__ void ldsm_x4_trans(uint32_t& r0, uint32_t& r1,
                                              uint32_t& r2, uint32_t& r3, uint32_t addr)
{
    asm volatile("ldmatrix.sync.aligned.m8n8.x4.trans.shared.b16 {%0,%1,%2,%3}, [%4];"
                 : "=r"(r0), "=r"(r1), "=r"(r2), "=r"(r3) : "r"(addr));
}

// ================= prologue kernels =========================================
__global__ __launch_bounds__(256)
void to_half(const float* __restrict__ in, __half* __restrict__ o, int n4)
{
    int i = blockIdx.x * blockDim.x + threadIdx.x;
    if (i < n4) {
        float4 t = ((const float4*)in)[i];
        __half2 lo = __floats2half2_rn(t.x, t.y);
        __half2 hi = __floats2half2_rn(t.z, t.w);
        ((uint2*)o)[i] = make_uint2(*(uint32_t*)&lo, *(uint32_t*)&hi);
    }
}

// all six W[K][N] -> Wt[N][K] (half) in one launch; job by blockIdx range
__global__ __launch_bounds__(256)
void transpose_all(const float* __restrict__ Wq, const float* __restrict__ Wk,
                   const float* __restrict__ Wv, const float* __restrict__ Wo,
                   const float* __restrict__ W1, const float* __restrict__ W2,
                   __half* __restrict__ wqkvt, __half* __restrict__ wot,
                   __half* __restrict__ w1t,   __half* __restrict__ w2t)
{
    const int bid = blockIdx.x;
    const float* W; __half* Wt; int K, N, tile;
    if      (bid < 256)  { W = Wq; Wt = wqkvt;              K = Ds;  N = Ds;  tile = bid; }
    else if (bid < 512)  { W = Wk; Wt = wqkvt + Ds * Ds;    K = Ds;  N = Ds;  tile = bid - 256; }
    else if (bid < 768)  { W = Wv; Wt = wqkvt + 2 * Ds * Ds;K = Ds;  N = Ds;  tile = bid - 512; }
    else if (bid < 1024) { W = Wo; Wt = wot;                K = Ds;  N = Ds;  tile = bid - 768; }
    else if (bid < 2048) { W = W1; Wt = w1t;                K = Ds;  N = FFs; tile = bid - 1024; }
    else                 { W = W2; Wt = w2t;                K = FFs; N = Ds;  tile = bid - 2048; }
    const int ntx = N / 32;
    const int nx = (tile % ntx) * 32, ky = (tile / ntx) * 32;

    __shared__ float t[32][33];
    const int x = threadIdx.x, y = threadIdx.y;   // 32 x 8
#pragma unroll
    for (int j = 0; j < 32; j += 8)
        t[y + j][x] = W[(size_t)(ky + y + j) * N + nx + x];
    __syncthreads();
#pragma unroll
    for (int j = 0; j < 32; j += 8)
        Wt[(size_t)(nx + y + j) * K + ky + x] = __float2half(t[x][y + j]);
}

__global__ void concat3(const float* __restrict__ a, const float* __restrict__ b,
                        const float* __restrict__ c, float* __restrict__ o)
{
    int i = blockIdx.x * blockDim.x + threadIdx.x;
    o[i] = (i < Ds) ? a[i] : (i < 2 * Ds) ? b[i - Ds] : c[i - 2 * Ds];
}

// ================= fp16 tensor-core GEMM ====================================
// C[M,N] = A[M,K] @ Bt[N,K]^T + bias.  256 thr, tile 128x128x64, warps 2x4.
// out_mode: 0 = fp32, 1 = fp32 rna-rounded, 2 = half
#define HST    72
#define HAS    (128 * HST)
#define HSTG   (2 * HAS)
#define HG_SMEM (2 * HSTG * 2)

__global__ __launch_bounds__(256)
void hgemm(const __half* __restrict__ A, const __half* __restrict__ Bt,
           const float* __restrict__ bias, void* __restrict__ Cv,
           int M, int N, int K, int relu, int out_mode)
{
    extern __shared__ __align__(256) __half sh[];
    const uint32_t sb = (uint32_t)__cvta_generic_to_shared(sh);

    const int tid  = threadIdx.x;
    const int lane = tid & 31;
    const int warp = tid >> 5;
    const int gid  = lane >> 2;
    const int tg   = lane & 3;
    const int wm   = (warp >> 2) * 64;
    const int wn   = (warp & 3) * 32;
    const int bm   = blockIdx.y * 128;
    const int bn   = blockIdx.x * 128;

    const int ar = tid >> 3;
    const int ac = (tid & 7) * 8;

    float d[4][4][4];
#pragma unroll
    for (int i = 0; i < 4; i++)
#pragma unroll
        for (int j = 0; j < 4; j++)
#pragma unroll
            for (int c = 0; c < 4; c++) d[i][j][c] = 0.f;

    auto do_load = [&](int stage, int k0) {
        const __half* pa = A  + (size_t)(bm + ar) * K + k0 + ac;
        const __half* pb = Bt + (size_t)(bn + ar) * K + k0 + ac;
        const uint32_t ba = sb + (uint32_t)stage * (HSTG * 2);
        const uint32_t bb = ba + HAS * 2;
#pragma unroll
        for (int i = 0; i < 4; i++) {
            uint32_t off = (uint32_t)((ar + 32 * i) * HST + ac) * 2;
            cp16(ba + off, pa + (size_t)32 * i * K);
            cp16(bb + off, pb + (size_t)32 * i * K);
        }
    };

    const int T = K / 64;
    do_load(0, 0);
    CP_COMMIT();

    int buf = 0;
    for (int t = 0; t < T; t++, buf ^= 1) {
        if (t + 1 < T) {
            do_load(buf ^ 1, (t + 1) * 64);
            CP_COMMIT();
            CP_WAIT(1);
        } else {
            CP_WAIT(0);
        }
        __syncthreads();

        const __half* pA = sh + buf * HSTG;
        const __half* pB = pA + HAS;
#pragma unroll
        for (int kk = 0; kk < 64; kk += 16) {
            uint32_t bf[4][2];
#pragma unroll
            for (int jn = 0; jn < 4; jn++) {
                const __half* bp = &pB[(wn + jn * 8 + gid) * HST + kk + 2 * tg];
                bf[jn][0] = *(const uint32_t*)bp;
                bf[jn][1] = *(const uint32_t*)(bp + 8);
            }
#pragma unroll
            for (int im = 0; im < 4; im++) {
                const __half* ap = &pA[(wm + im * 16 + gid) * HST + kk + 2 * tg];
                uint32_t a0 = *(const uint32_t*)ap;
                uint32_t a1 = *(const uint32_t*)(ap + 8 * HST);
                uint32_t a2 = *(const uint32_t*)(ap + 8);
                uint32_t a3 = *(const uint32_t*)(ap + 8 * HST + 8);
#pragma unroll
                for (int jn = 0; jn < 4; jn++)
                    mma_f16(d[im][jn], a0, a1, a2, a3, bf[jn][0], bf[jn][1]);
            }
        }
        __syncthreads();
    }

#pragma unroll
    for (int jn = 0; jn < 4; jn++) {
        const int col = bn + wn + jn * 8 + 2 * tg;
        float2 bv = *(const float2*)&bias[col];
#pragma unroll
        for (int im = 0; im < 4; im++) {
            const int row = bm + wm + im * 16 + gid;
            float v0 = d[im][jn][0] + bv.x, v1 = d[im][jn][1] + bv.y;
            float v2 = d[im][jn][2] + bv.x, v3 = d[im][jn][3] + bv.y;
            if (relu) {
                v0 = fmaxf(v0, 0.f); v1 = fmaxf(v1, 0.f);
                v2 = fmaxf(v2, 0.f); v3 = fmaxf(v3, 0.f);
            }
            if (out_mode == 2) {
                __half* Ch = (__half*)Cv;
                *(__half2*)&Ch[(size_t)row       * N + col] = __floats2half2_rn(v0, v1);
                *(__half2*)&Ch[(size_t)(row + 8) * N + col] = __floats2half2_rn(v2, v3);
            } else {
                if (out_mode == 1) { v0 = rna(v0); v1 = rna(v1); v2 = rna(v2); v3 = rna(v3); }
                float* Cf = (float*)Cv;
                *(float2*)&Cf[(size_t)row       * N + col] = make_float2(v0, v1);
                *(float2*)&Cf[(size_t)(row + 8) * N + col] = make_float2(v2, v3);
            }
        }
    }
}

// ============== banded attention, full fp16 m16n8k16 ========================
#define AST 72                                  // smem row stride in halves
#define ATTN_SMEM (3 * 64 * AST * 2)

__global__ __launch_bounds__(128)
void attn_f16(const __half* __restrict__ qkv, __half* __restrict__ out)
{
    extern __shared__ __half smh[];
    __half (*Qs)[AST] = (__half(*)[AST])smh;                 // also Ps
    __half (*Ks)[AST] = (__half(*)[AST])(smh + 64 * AST);
    const uint32_t sbase = (uint32_t)__cvta_generic_to_shared(smh);
    const uint32_t sbK = sbase + 64 * AST * 2;
    const uint32_t sbV = sbase + 2 * 64 * AST * 2;

    const int bh   = blockIdx.y;
    const int b    = bh >> 3;
    const int h    = bh & 7;
    const int q0   = blockIdx.x * 64;
    const int tid  = threadIdx.x;
    const int lane = tid & 31;
    const int warp = tid >> 5;
    const int gid  = lane >> 2;
    const int tg   = lane & 3;
    const int wm   = warp * 16;

    const int sr = tid >> 3;            // 0..15 rows per pass
    const int sc = (tid & 7) * 8;       // half offset (16B chunks)

    // ---- stage Q (half) ----
    {
        const __half* gq = qkv + ((size_t)(b * Ls + q0 + sr)) * QS + h * HDs + sc;
        const uint32_t dq = sbase + (uint32_t)(sr * AST + sc) * 2;
#pragma unroll
        for (int i = 0; i < 4; i++)
            cp16(dq + i * (16 * AST * 2), gq + (size_t)16 * i * QS);
    }
    CP_COMMIT();
    CP_WAIT(0);
    __syncthreads();

    // ---- Q fragments (4 k16 chunks) ----
    uint32_t qa[4][4];
#pragma unroll
    for (int kc = 0; kc < 4; kc++) {
        const __half* p0 = &Qs[wm + gid    ][kc * 16 + 2 * tg];
        const __half* p1 = &Qs[wm + gid + 8][kc * 16 + 2 * tg];
        qa[kc][0] = *(const uint32_t*)p0;
        qa[kc][1] = *(const uint32_t*)p1;
        qa[kc][2] = *(const uint32_t*)(p0 + 8);
        qa[kc][3] = *(const uint32_t*)(p1 + 8);
    }

    float o[8][4];
#pragma unroll
    for (int jn = 0; jn < 8; jn++)
#pragma unroll
        for (int c = 0; c < 4; c++) o[jn][c] = 0.f;
    float m0 = -1e30f, m1 = -1e30f, l0 = 0.f, l1 = 0.f;

    const int row0 = q0 + wm + gid;
    const int row1 = row0 + 8;
    const int kstart = max(0, q0 - WIN);
    const int kend   = min(Ls, q0 + 64 + WIN);

    // ldmatrix V address pieces (per-thread)
    const int vkey = ((lane >> 3) & 1) * 8 + (lane & 7);
    const int vdim = ((lane >> 4) & 1) * 8;

    for (int kt = kstart; kt < kend; kt += 64) {
        __syncthreads();
        {
            const __half* gk = qkv + ((size_t)(b * Ls + kt + sr)) * QS + Ds     + h * HDs + sc;
            const __half* gv = qkv + ((size_t)(b * Ls + kt + sr)) * QS + 2 * Ds + h * HDs + sc;
            const uint32_t dk = sbK + (uint32_t)(sr * AST + sc) * 2;
            const uint32_t dv = sbV + (uint32_t)(sr * AST + sc) * 2;
#pragma unroll
            for (int i = 0; i < 4; i++) {
                cp16(dk + i * (16 * AST * 2), gk + (size_t)16 * i * QS);
                cp16(dv + i * (16 * AST * 2), gv + (size_t)16 * i * QS);
            }
        }
        CP_COMMIT();
        CP_WAIT(0);
        __syncthreads();

        // ---- S = Q K^T (fp16 mma, fp32 accum) ----
        float s[8][4];
#pragma unroll
        for (int jn = 0; jn < 8; jn++)
#pragma unroll
            for (int c = 0; c < 4; c++) s[jn][c] = 0.f;

#pragma unroll
        for (int kc = 0; kc < 4; kc++) {
#pragma unroll
            for (int jn = 0; jn < 8; jn++) {
                const __half* bp = &Ks[jn * 8 + gid][kc * 16 + 2 * tg];
                uint32_t b0 = *(const uint32_t*)bp;
                uint32_t b1 = *(const uint32_t*)(bp + 8);
                mma_f16(s[jn], qa[kc][0], qa[kc][1], qa[kc][2], qa[kc][3], b0, b1);
            }
        }

        // ---- scale + band mask + row max ----
        float rmax0 = -1e30f, rmax1 = -1e30f;
#pragma unroll
        for (int jn = 0; jn < 8; jn++) {
            int cb = kt + jn * 8 + 2 * tg;
            s[jn][0] = (abs(cb     - row0) <= WIN) ? s[jn][0] * 0.125f : -1e30f;
            s[jn][1] = (abs(cb + 1 - row0) <= WIN) ? s[jn][1] * 0.125f : -1e30f;
            s[jn][2] = (abs(cb     - row1) <= WIN) ? s[jn][2] * 0.125f : -1e30f;
            s[jn][3] = (abs(cb + 1 - row1) <= WIN) ? s[jn][3] * 0.125f : -1e30f;
            rmax0 = fmaxf(rmax0, fmaxf(s[jn][0], s[jn][1]));
            rmax1 = fmaxf(rmax1, fmaxf(s[jn][2], s[jn][3]));
        }
        rmax0 = fmaxf(rmax0, __shfl_xor_sync(0xffffffffu, rmax0, 1));
        rmax0 = fmaxf(rmax0, __shfl_xor_sync(0xffffffffu, rmax0, 2));
        rmax1 = fmaxf(rmax1, __shfl_xor_sync(0xffffffffu, rmax1, 1));
        rmax1 = fmaxf(rmax1, __shfl_xor_sync(0xffffffffu, rmax1, 2));

        float mn0 = fmaxf(m0, rmax0);
        float mn1 = fmaxf(m1, rmax1);
        float sc0 = __expf(m0 - mn0);
        float sc1 = __expf(m1 - mn1);
        m0 = mn0; m1 = mn1;
        l0 *= sc0; l1 *= sc1;
#pragma unroll
        for (int jn = 0; jn < 8; jn++) {
            o[jn][0] *= sc0; o[jn][1] *= sc0;
            o[jn][2] *= sc1; o[jn][3] *= sc1;
        }

        // ---- P = exp(S - m) -> half in Ps; accumulate l ----
#pragma unroll
        for (int jn = 0; jn < 8; jn++) {
            float p0 = __expf(s[jn][0] - m0);
            float p1 = __expf(s[jn][1] - m0);
            float p2 = __expf(s[jn][2] - m1);
            float p3 = __expf(s[jn][3] - m1);
            l0 += p0 + p1;
            l1 += p2 + p3;
            *(__half2*)&Qs[wm + gid    ][jn * 8 + 2 * tg] = __floats2half2_rn(p0, p1);
            *(__half2*)&Qs[wm + gid + 8][jn * 8 + 2 * tg] = __floats2half2_rn(p2, p3);
        }
        __syncwarp();   // warp reads only its own 16 P rows

        // ---- O += P V  (V^T fragments via ldmatrix.trans) ----
#pragma unroll
        for (int kc = 0; kc < 4; kc++) {
            const __half* pp0 = &Qs[wm + gid    ][kc * 16 + 2 * tg];
            const __half* pp1 = &Qs[wm + gid + 8][kc * 16 + 2 * tg];
            uint32_t a0 = *(const uint32_t*)pp0;
            uint32_t a1 = *(const uint32_t*)pp1;
            uint32_t a2 = *(const uint32_t*)(pp0 + 8);
            uint32_t a3 = *(const uint32_t*)(pp1 + 8);
#pragma unroll
            for (int jp = 0; jp < 4; jp++) {
                uint32_t vaddr = sbV + (uint32_t)((kc * 16 + vkey) * AST + jp * 16 + vdim) * 2;
                uint32_t b0, b1, b2, b3;
                ldsm_x4_trans(b0, b1, b2, b3, vaddr);
                mma_f16(o[jp * 2    ], a0, a1, a2, a3, b0, b1);
                mma_f16(o[jp * 2 + 1], a0, a1, a2, a3, b2, b3);
            }
        }
    }

    l0 += __shfl_xor_sync(0xffffffffu, l0, 1);
    l0 += __shfl_xor_sync(0xffffffffu, l0, 2);
    l1 += __shfl_xor_sync(0xffffffffu, l1, 1);
    l1 += __shfl_xor_sync(0xffffffffu, l1, 2);
    const float inv0 = 1.f / l0;
    const float inv1 = 1.f / l1;

    __half* o0 = out + ((size_t)(b * Ls + row0)) * Ds + h * HDs;
    __half* o1 = out + ((size_t)(b * Ls + row1)) * Ds + h * HDs;
#pragma unroll
    for (int jn = 0; jn < 8; jn++) {
        int c = jn * 8 + 2 * tg;
        *(__half2*)&o0[c] = __floats2half2_rn(o[jn][0] * inv0, o[jn][1] * inv0);
        *(__half2*)&o1[c] = __floats2half2_rn(o[jn][2] * inv1, o[jn][3] * inv1);
    }
}

// ---------------- residual + LayerNorm (optional half twin) -----------------
__global__ __launch_bounds__(128)
void add_ln(const float* __restrict__ x, const float* __restrict__ r,
            const float* __restrict__ g, const float* __restrict__ bta,
            float* __restrict__ out, __half* __restrict__ out_r)
{
    const int row = blockIdx.x;
    const int tid = threadIdx.x;
    const float* xr = x + (size_t)row * Ds;
    const float* rr = r + (size_t)row * Ds;

    __shared__ float t[Ds];
    __shared__ float s1[4], s2[4];

    float s = 0.f, ss = 0.f;
#pragma unroll
    for (int i = 0; i < 4; i++) {
        int c = tid + i * 128;
        float u = xr[c] + rr[c];
        t[c] = u;
        s += u;
        ss = fmaf(u, u, ss);
    }
#pragma unroll
    for (int o = 16; o; o >>= 1) {
        s  += __shfl_xor_sync(0xffffffffu, s,  o);
        ss += __shfl_xor_sync(0xffffffffu, ss, o);
    }
    if ((tid & 31) == 0) { s1[tid >> 5] = s; s2[tid >> 5] = ss; }
    __syncthreads();
    float S  = s1[0] + s1[1] + s1[2] + s1[3];
    float SS = s2[0] + s2[1] + s2[2] + s2[3];
    float mu   = S * (1.f / Ds);
    float var  = SS * (1.f / Ds) - mu * mu;
    float rstd = rsqrtf(var + 1e-5f);
#pragma unroll
    for (int i = 0; i < 4; i++) {
        int c = tid + i * 128;
        float val = (t[c] - mu) * rstd * g[c] + bta[c];
        out[(size_t)row * Ds + c] = val;
        if (out_r) out_r[(size_t)row * Ds + c] = __float2half(val);
    }
}

// ---------------- launch ----------------------------------------------------
extern "C" void kernel_launch(void* const* d_in, const int* in_sizes, int n_in,
                              void* d_out, int out_size)
{
    const float* x    = (const float*)d_in[0];
    const float* Wq   = (const float*)d_in[1];
    const float* bq   = (const float*)d_in[2];
    const float* Wk   = (const float*)d_in[3];
    const float* bk   = (const float*)d_in[4];
    const float* Wv   = (const float*)d_in[5];
    const float* bv   = (const float*)d_in[6];
    const float* Wo   = (const float*)d_in[7];
    const float* bo   = (const float*)d_in[8];
    const float* ln1g = (const float*)d_in[9];
    const float* ln1b = (const float*)d_in[10];
    const float* W1   = (const float*)d_in[11];
    const float* b1   = (const float*)d_in[12];
    const float* W2   = (const float*)d_in[13];
    const float* b2   = (const float*)d_in[14];
    const float* ln2g = (const float*)d_in[15];
    const float* ln2b = (const float*)d_in[16];
    float* out = (float*)d_out;

    __half *xh, *qkv, *att, *hr, *ff1, *wqkvt, *wot, *w1t, *w2t;
    float  *prj, *h, *ff2, *bqkv;
    cudaGetSymbolAddress((void**)&xh,    g_xh);
    cudaGetSymbolAddress((void**)&qkv,   g_qkv);
    cudaGetSymbolAddress((void**)&att,   g_att);
    cudaGetSymbolAddress((void**)&prj,   g_prj);
    cudaGetSymbolAddress((void**)&h,     g_h);
    cudaGetSymbolAddress((void**)&hr,    g_hr);
    cudaGetSymbolAddress((void**)&ff1,   g_ff1);
    cudaGetSymbolAddress((void**)&ff2,   g_ff2);
    cudaGetSymbolAddress((void**)&wqkvt, g_wqkvt);
    cudaGetSymbolAddress((void**)&wot,   g_wot);
    cudaGetSymbolAddress((void**)&w1t,   g_w1t);
    cudaGetSymbolAddress((void**)&w2t,   g_w2t);
    cudaGetSymbolAddress((void**)&bqkv,  g_bqkv);

    cudaFuncSetAttribute(hgemm,    cudaFuncAttributeMaxDynamicSharedMemorySize, HG_SMEM);
    cudaFuncSetAttribute(attn_f16, cudaFuncAttributeMaxDynamicSharedMemorySize, ATTN_SMEM);

    // prologue
    to_half<<<(Ms * Ds / 4 + 255) / 256, 256>>>(x, xh, Ms * Ds / 4);
    transpose_all<<<3072, dim3(32, 8)>>>(Wq, Wk, Wv, Wo, W1, W2, wqkvt, wot, w1t, w2t);
    concat3<<<3, 512>>>(bq, bk, bv, bqkv);

    // fused QKV -> half
    hgemm<<<dim3(QS / 128, Ms / 128), 256, HG_SMEM>>>(xh, wqkvt, bqkv, qkv,
                                                      Ms, QS, Ds, 0, 2);

    attn_f16<<<dim3(Ls / 64, Bb * Hh), 128, ATTN_SMEM>>>(qkv, att);

    hgemm<<<dim3(Ds / 128, Ms / 128), 256, HG_SMEM>>>(att, wot, bo, prj,
                                                      Ms, Ds, Ds, 0, 0);
    add_ln<<<Ms, 128>>>(x, prj, ln1g, ln1b, h, hr);

    hgemm<<<dim3(FFs / 128, Ms / 128), 256, HG_SMEM>>>(hr, w1t, b1, ff1,
                                                       Ms, FFs, Ds, 1, 2);
    hgemm<<<dim3(Ds / 128, Ms / 128), 256, HG_SMEM>>>(ff1, w2t, b2, ff2,
                                                      Ms, Ds, FFs, 0, 0);
    add_ln<<<Ms, 128>>>(h, ff2, ln2g, ln2b, out, nullptr);
}

// round 9
// speedup vs baseline: 1.7513x; 1.0114x over previous
#include <cuda_runtime.h>
#include <cuda_fp16.h>
#include <cstdint>

#define Bb  2
#define Ls  4096
#define Ds  512
#define Hh  8
#define HDs 64
#define FFs 2048
#define WIN 128
#define Ms  (Bb*Ls)
#define QS  1536     // fused qkv row stride (q|k|v) in halves

// ---------------- scratch (device globals: allocation-guard safe) ----------
__device__ __half g_xh  [Ms*Ds];
__device__ __half g_qkv [Ms*QS];
__device__ __half g_att [Ms*Ds];
__device__ float  g_prj [Ms*Ds];
__device__ float  g_h   [Ms*Ds];
__device__ __half g_hr  [Ms*Ds];
__device__ __half g_ff1 [Ms*FFs];
__device__ float  g_ff2 [Ms*Ds];
__device__ __half g_wqkvt[3*Ds*Ds];
__device__ __half g_wot [Ds*Ds];
__device__ __half g_w1t [Ds*FFs];
__device__ __half g_w2t [FFs*Ds];
__device__ float  g_bqkv[QS];

// ---------------- helpers ---------------------------------------------------
__device__ __forceinline__ void cp16(uint32_t dst_smem, const void* src) {
    asm volatile("cp.async.ca.shared.global [%0], [%1], 16;\n"
                 :: "r"(dst_smem), "l"(src));
}
#define CP_COMMIT() asm volatile("cp.async.commit_group;\n")
#define CP_WAIT(n)  asm volatile("cp.async.wait_group %0;\n" :: "n"(n))

__device__ __forceinline__ uint32_t f2tf(float x) {
    uint32_t u;
    asm("cvt.rna.tf32.f32 %0, %1;" : "=r"(u) : "f"(x));
    return u;
}
__device__ __forceinline__ float rna(float x) { return __uint_as_float(f2tf(x)); }

__device__ __forceinline__ void mma_f16(float d[4],
    uint32_t a0, uint32_t a1, uint32_t a2, uint32_t a3, uint32_t b0, uint32_t b1)
{
    asm volatile(
        "mma.sync.aligned.m16n8k16.row.col.f32.f16.f16.f32 "
        "{%0,%1,%2,%3}, {%4,%5,%6,%7}, {%8,%9}, {%0,%1,%2,%3};\n"
        : "+f"(d[0]), "+f"(d[1]), "+f"(d[2]), "+f"(d[3])
        : "r"(a0), "r"(a1), "r"(a2), "r"(a3), "r"(b0), "r"(b1));
}

__device__ __forceinline__ void ldsm_x4(uint32_t r[4], uint32_t addr)
{
    asm volatile("ldmatrix.sync.aligned.m8n8.x4.shared.b16 {%0,%1,%2,%3}, [%4];"
                 : "=r"(r[0]), "=r"(r[1]), "=r"(r[2]), "=r"(r[3]) : "r"(addr));
}
__device__ __forceinline__ void ldsm_x4_trans(uint32_t& r0, uint32_t& r1,
                                              uint32_t& r2, uint32_t& r3, uint32_t addr)
{
    asm volatile("ldmatrix.sync.aligned.m8n8.x4.trans.shared.b16 {%0,%1,%2,%3}, [%4];"
                 : "=r"(r0), "=r"(r1), "=r"(r2), "=r"(r3) : "r"(addr));
}

// ================= prologue kernels =========================================
__global__ __launch_bounds__(256)
void to_half(const float* __restrict__ in, __half* __restrict__ o, int n4)
{
    int i = blockIdx.x * blockDim.x + threadIdx.x;
    if (i < n4) {
        float4 t = ((const float4*)in)[i];
        __half2 lo = __floats2half2_rn(t.x, t.y);
        __half2 hi = __floats2half2_rn(t.z, t.w);
        ((uint2*)o)[i] = make_uint2(*(uint32_t*)&lo, *(uint32_t*)&hi);
    }
}

// all six W[K][N] -> Wt[N][K] (half) in one launch
__global__ __launch_bounds__(256)
void transpose_all(const float* __restrict__ Wq, const float* __restrict__ Wk,
                   const float* __restrict__ Wv, const float* __restrict__ Wo,
                   const float* __restrict__ W1, const float* __restrict__ W2,
                   __half* __restrict__ wqkvt, __half* __restrict__ wot,
                   __half* __restrict__ w1t,   __half* __restrict__ w2t)
{
    const int bid = blockIdx.x;
    const float* W; __half* Wt; int K, N, tile;
    if      (bid < 256)  { W = Wq; Wt = wqkvt;               K = Ds;  N = Ds;  tile = bid; }
    else if (bid < 512)  { W = Wk; Wt = wqkvt + Ds * Ds;     K = Ds;  N = Ds;  tile = bid - 256; }
    else if (bid < 768)  { W = Wv; Wt = wqkvt + 2 * Ds * Ds; K = Ds;  N = Ds;  tile = bid - 512; }
    else if (bid < 1024) { W = Wo; Wt = wot;                 K = Ds;  N = Ds;  tile = bid - 768; }
    else if (bid < 2048) { W = W1; Wt = w1t;                 K = Ds;  N = FFs; tile = bid - 1024; }
    else                 { W = W2; Wt = w2t;                 K = FFs; N = Ds;  tile = bid - 2048; }
    const int ntx = N / 32;
    const int nx = (tile % ntx) * 32, ky = (tile / ntx) * 32;

    __shared__ float t[32][33];
    const int x = threadIdx.x, y = threadIdx.y;
#pragma unroll
    for (int j = 0; j < 32; j += 8)
        t[y + j][x] = W[(size_t)(ky + y + j) * N + nx + x];
    __syncthreads();
#pragma unroll
    for (int j = 0; j < 32; j += 8)
        Wt[(size_t)(nx + y + j) * K + ky + x] = __float2half(t[x][y + j]);
}

__global__ void concat3(const float* __restrict__ a, const float* __restrict__ b,
                        const float* __restrict__ c, float* __restrict__ o)
{
    int i = blockIdx.x * blockDim.x + threadIdx.x;
    o[i] = (i < Ds) ? a[i] : (i < 2 * Ds) ? b[i - Ds] : c[i - 2 * Ds];
}

// ================= fp16 tensor-core GEMM ====================================
// C[M,N] = A[M,K] @ Bt[N,K]^T + bias.  256 thr, tile 128x128x64, warps 2x4.
// 3-stage cp.async pipeline, ldmatrix fragment loads.
// out_mode: 0 = fp32, 1 = fp32 rna-rounded, 2 = half
#define HST    72
#define HAS    (128 * HST)
#define HSTG   (2 * HAS)                  // halves per stage (A+B)
#define HG_SMEM (3 * HSTG * 2)            // 3 stages

__global__ __launch_bounds__(256)
void hgemm(const __half* __restrict__ A, const __half* __restrict__ Bt,
           const float* __restrict__ bias, void* __restrict__ Cv,
           int M, int N, int K, int relu, int out_mode)
{
    extern __shared__ __align__(256) __half sh[];
    const uint32_t sb = (uint32_t)__cvta_generic_to_shared(sh);

    const int tid  = threadIdx.x;
    const int lane = tid & 31;
    const int warp = tid >> 5;
    const int gid  = lane >> 2;
    const int tg   = lane & 3;
    const int wm   = (warp >> 2) * 64;
    const int wn   = (warp & 3) * 32;
    const int bm   = blockIdx.y * 128;
    const int bn   = blockIdx.x * 128;

    const int ar = tid >> 3;
    const int ac = (tid & 7) * 8;

    // ldmatrix lane offsets
    const int a_row = wm + ((lane >> 3) & 1) * 8 + (lane & 7);   // + im*16
    const int a_k   = ((lane >> 4) & 1) * 8;                     // + kk
    const int b_row = wn + ((lane >> 4) & 1) * 8 + (lane & 7);   // + jp*16
    const int b_k   = ((lane >> 3) & 1) * 8;                     // + kk

    float d[4][4][4];
#pragma unroll
    for (int i = 0; i < 4; i++)
#pragma unroll
        for (int j = 0; j < 4; j++)
#pragma unroll
            for (int c = 0; c < 4; c++) d[i][j][c] = 0.f;

    auto do_load = [&](int stage, int k0) {
        const __half* pa = A  + (size_t)(bm + ar) * K + k0 + ac;
        const __half* pb = Bt + (size_t)(bn + ar) * K + k0 + ac;
        const uint32_t ba = sb + (uint32_t)stage * (HSTG * 2);
        const uint32_t bb = ba + HAS * 2;
#pragma unroll
        for (int i = 0; i < 4; i++) {
            uint32_t off = (uint32_t)((ar + 32 * i) * HST + ac) * 2;
            cp16(ba + off, pa + (size_t)32 * i * K);
            cp16(bb + off, pb + (size_t)32 * i * K);
        }
    };

    const int T = K / 64;
    do_load(0, 0);
    CP_COMMIT();
    if (T > 1) { do_load(1, 64); CP_COMMIT(); }

    for (int t = 0; t < T; t++) {
        if (t + 1 < T) { CP_WAIT(1); } else { CP_WAIT(0); }
        __syncthreads();

        const int buf = t % 3;
        const uint32_t sA = sb + (uint32_t)buf * (HSTG * 2);
        const uint32_t sB = sA + HAS * 2;

#pragma unroll
        for (int kk = 0; kk < 64; kk += 16) {
            uint32_t af[4][4], bf[2][4];
#pragma unroll
            for (int im = 0; im < 4; im++)
                ldsm_x4(af[im], sA + (uint32_t)((a_row + im * 16) * HST + kk + a_k) * 2);
#pragma unroll
            for (int jp = 0; jp < 2; jp++)
                ldsm_x4(bf[jp], sB + (uint32_t)((b_row + jp * 16) * HST + kk + b_k) * 2);
#pragma unroll
            for (int im = 0; im < 4; im++)
#pragma unroll
                for (int jn = 0; jn < 4; jn++)
                    mma_f16(d[im][jn], af[im][0], af[im][1], af[im][2], af[im][3],
                            bf[jn >> 1][(jn & 1) * 2], bf[jn >> 1][(jn & 1) * 2 + 1]);
        }

        if (t + 2 < T) { do_load((t + 2) % 3, (t + 2) * 64); CP_COMMIT(); }
    }

    // epilogue
#pragma unroll
    for (int jn = 0; jn < 4; jn++) {
        const int col = bn + wn + jn * 8 + 2 * tg;
        float2 bv = *(const float2*)&bias[col];
#pragma unroll
        for (int im = 0; im < 4; im++) {
            const int row = bm + wm + im * 16 + gid;
            float v0 = d[im][jn][0] + bv.x, v1 = d[im][jn][1] + bv.y;
            float v2 = d[im][jn][2] + bv.x, v3 = d[im][jn][3] + bv.y;
            if (relu) {
                v0 = fmaxf(v0, 0.f); v1 = fmaxf(v1, 0.f);
                v2 = fmaxf(v2, 0.f); v3 = fmaxf(v3, 0.f);
            }
            if (out_mode == 2) {
                __half* Ch = (__half*)Cv;
                *(__half2*)&Ch[(size_t)row       * N + col] = __floats2half2_rn(v0, v1);
                *(__half2*)&Ch[(size_t)(row + 8) * N + col] = __floats2half2_rn(v2, v3);
            } else {
                if (out_mode == 1) { v0 = rna(v0); v1 = rna(v1); v2 = rna(v2); v3 = rna(v3); }
                float* Cf = (float*)Cv;
                *(float2*)&Cf[(size_t)row       * N + col] = make_float2(v0, v1);
                *(float2*)&Cf[(size_t)(row + 8) * N + col] = make_float2(v2, v3);
            }
        }
    }
}

// ============== banded attention, full fp16 m16n8k16 ========================
#define AST 72
#define ATTN_SMEM (3 * 64 * AST * 2)

__global__ __launch_bounds__(128)
void attn_f16(const __half* __restrict__ qkv, __half* __restrict__ out)
{
    extern __shared__ __half smh[];
    __half (*Qs)[AST] = (__half(*)[AST])smh;                 // also Ps
    __half (*Ks)[AST] = (__half(*)[AST])(smh + 64 * AST);
    const uint32_t sbase = (uint32_t)__cvta_generic_to_shared(smh);
    const uint32_t sbK = sbase + 64 * AST * 2;
    const uint32_t sbV = sbase + 2 * 64 * AST * 2;

    const int bh   = blockIdx.y;
    const int b    = bh >> 3;
    const int h    = bh & 7;
    const int q0   = blockIdx.x * 64;
    const int tid  = threadIdx.x;
    const int lane = tid & 31;
    const int warp = tid >> 5;
    const int gid  = lane >> 2;
    const int tg   = lane & 3;
    const int wm   = warp * 16;

    const int sr = tid >> 3;
    const int sc = (tid & 7) * 8;

    {
        const __half* gq = qkv + ((size_t)(b * Ls + q0 + sr)) * QS + h * HDs + sc;
        const uint32_t dq = sbase + (uint32_t)(sr * AST + sc) * 2;
#pragma unroll
        for (int i = 0; i < 4; i++)
            cp16(dq + i * (16 * AST * 2), gq + (size_t)16 * i * QS);
    }
    CP_COMMIT();
    CP_WAIT(0);
    __syncthreads();

    uint32_t qa[4][4];
#pragma unroll
    for (int kc = 0; kc < 4; kc++) {
        const __half* p0 = &Qs[wm + gid    ][kc * 16 + 2 * tg];
        const __half* p1 = &Qs[wm + gid + 8][kc * 16 + 2 * tg];
        qa[kc][0] = *(const uint32_t*)p0;
        qa[kc][1] = *(const uint32_t*)p1;
        qa[kc][2] = *(const uint32_t*)(p0 + 8);
        qa[kc][3] = *(const uint32_t*)(p1 + 8);
    }

    float o[8][4];
#pragma unroll
    for (int jn = 0; jn < 8; jn++)
#pragma unroll
        for (int c = 0; c < 4; c++) o[jn][c] = 0.f;
    float m0 = -1e30f, m1 = -1e30f, l0 = 0.f, l1 = 0.f;

    const int row0 = q0 + wm + gid;
    const int row1 = row0 + 8;
    const int kstart = max(0, q0 - WIN);
    const int kend   = min(Ls, q0 + 64 + WIN);

    const int vkey = ((lane >> 3) & 1) * 8 + (lane & 7);
    const int vdim = ((lane >> 4) & 1) * 8;

    for (int kt = kstart; kt < kend; kt += 64) {
        __syncthreads();
        {
            const __half* gk = qkv + ((size_t)(b * Ls + kt + sr)) * QS + Ds     + h * HDs + sc;
            const __half* gv = qkv + ((size_t)(b * Ls + kt + sr)) * QS + 2 * Ds + h * HDs + sc;
            const uint32_t dk = sbK + (uint32_t)(sr * AST + sc) * 2;
            const uint32_t dv = sbV + (uint32_t)(sr * AST + sc) * 2;
#pragma unroll
            for (int i = 0; i < 4; i++) {
                cp16(dk + i * (16 * AST * 2), gk + (size_t)16 * i * QS);
                cp16(dv + i * (16 * AST * 2), gv + (size_t)16 * i * QS);
            }
        }
        CP_COMMIT();
        CP_WAIT(0);
        __syncthreads();

        float s[8][4];
#pragma unroll
        for (int jn = 0; jn < 8; jn++)
#pragma unroll
            for (int c = 0; c < 4; c++) s[jn][c] = 0.f;

#pragma unroll
        for (int kc = 0; kc < 4; kc++) {
#pragma unroll
            for (int jn = 0; jn < 8; jn++) {
                const __half* bp = &Ks[jn * 8 + gid][kc * 16 + 2 * tg];
                uint32_t b0 = *(const uint32_t*)bp;
                uint32_t b1 = *(const uint32_t*)(bp + 8);
                mma_f16(s[jn], qa[kc][0], qa[kc][1], qa[kc][2], qa[kc][3], b0, b1);
            }
        }

        float rmax0 = -1e30f, rmax1 = -1e30f;
#pragma unroll
        for (int jn = 0; jn < 8; jn++) {
            int cb = kt + jn * 8 + 2 * tg;
            s[jn][0] = (abs(cb     - row0) <= WIN) ? s[jn][0] * 0.125f : -1e30f;
            s[jn][1] = (abs(cb + 1 - row0) <= WIN) ? s[jn][1] * 0.125f : -1e30f;
            s[jn][2] = (abs(cb     - row1) <= WIN) ? s[jn][2] * 0.125f : -1e30f;
            s[jn][3] = (abs(cb + 1 - row1) <= WIN) ? s[jn][3] * 0.125f : -1e30f;
            rmax0 = fmaxf(rmax0, fmaxf(s[jn][0], s[jn][1]));
            rmax1 = fmaxf(rmax1, fmaxf(s[jn][2], s[jn][3]));
        }
        rmax0 = fmaxf(rmax0, __shfl_xor_sync(0xffffffffu, rmax0, 1));
        rmax0 = fmaxf(rmax0, __shfl_xor_sync(0xffffffffu, rmax0, 2));
        rmax1 = fmaxf(rmax1, __shfl_xor_sync(0xffffffffu, rmax1, 1));
        rmax1 = fmaxf(rmax1, __shfl_xor_sync(0xffffffffu, rmax1, 2));

        float mn0 = fmaxf(m0, rmax0);
        float mn1 = fmaxf(m1, rmax1);
        float sc0 = __expf(m0 - mn0);
        float sc1 = __expf(m1 - mn1);
        m0 = mn0; m1 = mn1;
        l0 *= sc0; l1 *= sc1;
#pragma unroll
        for (int jn = 0; jn < 8; jn++) {
            o[jn][0] *= sc0; o[jn][1] *= sc0;
            o[jn][2] *= sc1; o[jn][3] *= sc1;
        }

#pragma unroll
        for (int jn = 0; jn < 8; jn++) {
            float p0 = __expf(s[jn][0] - m0);
            float p1 = __expf(s[jn][1] - m0);
            float p2 = __expf(s[jn][2] - m1);
            float p3 = __expf(s[jn][3] - m1);
            l0 += p0 + p1;
            l1 += p2 + p3;
            *(__half2*)&Qs[wm + gid    ][jn * 8 + 2 * tg] = __floats2half2_rn(p0, p1);
            *(__half2*)&Qs[wm + gid + 8][jn * 8 + 2 * tg] = __floats2half2_rn(p2, p3);
        }
        __syncwarp();

#pragma unroll
        for (int kc = 0; kc < 4; kc++) {
            const __half* pp0 = &Qs[wm + gid    ][kc * 16 + 2 * tg];
            const __half* pp1 = &Qs[wm + gid + 8][kc * 16 + 2 * tg];
            uint32_t a0 = *(const uint32_t*)pp0;
            uint32_t a1 = *(const uint32_t*)pp1;
            uint32_t a2 = *(const uint32_t*)(pp0 + 8);
            uint32_t a3 = *(const uint32_t*)(pp1 + 8);
#pragma unroll
            for (int jp = 0; jp < 4; jp++) {
                uint32_t vaddr = sbV + (uint32_t)((kc * 16 + vkey) * AST + jp * 16 + vdim) * 2;
                uint32_t b0, b1, b2, b3;
                ldsm_x4_trans(b0, b1, b2, b3, vaddr);
                mma_f16(o[jp * 2    ], a0, a1, a2, a3, b0, b1);
                mma_f16(o[jp * 2 + 1], a0, a1, a2, a3, b2, b3);
            }
        }
    }

    l0 += __shfl_xor_sync(0xffffffffu, l0, 1);
    l0 += __shfl_xor_sync(0xffffffffu, l0, 2);
    l1 += __shfl_xor_sync(0xffffffffu, l1, 1);
    l1 += __shfl_xor_sync(0xffffffffu, l1, 2);
    const float inv0 = 1.f / l0;
    const float inv1 = 1.f / l1;

    __half* o0 = out + ((size_t)(b * Ls + row0)) * Ds + h * HDs;
    __half* o1 = out + ((size_t)(b * Ls + row1)) * Ds + h * HDs;
#pragma unroll
    for (int jn = 0; jn < 8; jn++) {
        int c = jn * 8 + 2 * tg;
        *(__half2*)&o0[c] = __floats2half2_rn(o[jn][0] * inv0, o[jn][1] * inv0);
        *(__half2*)&o1[c] = __floats2half2_rn(o[jn][2] * inv1, o[jn][3] * inv1);
    }
}

// ---------------- residual + LayerNorm (optional half twin) -----------------
__global__ __launch_bounds__(128)
void add_ln(const float* __restrict__ x, const float* __restrict__ r,
            const float* __restrict__ g, const float* __restrict__ bta,
            float* __restrict__ out, __half* __restrict__ out_r)
{
    const int row = blockIdx.x;
    const int tid = threadIdx.x;
    const float* xr = x + (size_t)row * Ds;
    const float* rr = r + (size_t)row * Ds;

    __shared__ float t[Ds];
    __shared__ float s1[4], s2[4];

    float s = 0.f, ss = 0.f;
#pragma unroll
    for (int i = 0; i < 4; i++) {
        int c = tid + i * 128;
        float u = xr[c] + rr[c];
        t[c] = u;
        s += u;
        ss = fmaf(u, u, ss);
    }
#pragma unroll
    for (int o = 16; o; o >>= 1) {
        s  += __shfl_xor_sync(0xffffffffu, s,  o);
        ss += __shfl_xor_sync(0xffffffffu, ss, o);
    }
    if ((tid & 31) == 0) { s1[tid >> 5] = s; s2[tid >> 5] = ss; }
    __syncthreads();
    float S  = s1[0] + s1[1] + s1[2] + s1[3];
    float SS = s2[0] + s2[1] + s2[2] + s2[3];
    float mu   = S * (1.f / Ds);
    float var  = SS * (1.f / Ds) - mu * mu;
    float rstd = rsqrtf(var + 1e-5f);
#pragma unroll
    for (int i = 0; i < 4; i++) {
        int c = tid + i * 128;
        float val = (t[c] - mu) * rstd * g[c] + bta[c];
        out[(size_t)row * Ds + c] = val;
        if (out_r) out_r[(size_t)row * Ds + c] = __float2half(val);
    }
}

// ---------------- launch ----------------------------------------------------
extern "C" void kernel_launch(void* const* d_in, const int* in_sizes, int n_in,
                              void* d_out, int out_size)
{
    const float* x    = (const float*)d_in[0];
    const float* Wq   = (const float*)d_in[1];
    const float* bq   = (const float*)d_in[2];
    const float* Wk   = (const float*)d_in[3];
    const float* bk   = (const float*)d_in[4];
    const float* Wv   = (const float*)d_in[5];
    const float* bv   = (const float*)d_in[6];
    const float* Wo   = (const float*)d_in[7];
    const float* bo   = (const float*)d_in[8];
    const float* ln1g = (const float*)d_in[9];
    const float* ln1b = (const float*)d_in[10];
    const float* W1   = (const float*)d_in[11];
    const float* b1   = (const float*)d_in[12];
    const float* W2   = (const float*)d_in[13];
    const float* b2   = (const float*)d_in[14];
    const float* ln2g = (const float*)d_in[15];
    const float* ln2b = (const float*)d_in[16];
    float* out = (float*)d_out;

    __half *xh, *qkv, *att, *hr, *ff1, *wqkvt, *wot, *w1t, *w2t;
    float  *prj, *h, *ff2, *bqkv;
    cudaGetSymbolAddress((void**)&xh,    g_xh);
    cudaGetSymbolAddress((void**)&qkv,   g_qkv);
    cudaGetSymbolAddress((void**)&att,   g_att);
    cudaGetSymbolAddress((void**)&prj,   g_prj);
    cudaGetSymbolAddress((void**)&h,     g_h);
    cudaGetSymbolAddress((void**)&hr,    g_hr);
    cudaGetSymbolAddress((void**)&ff1,   g_ff1);
    cudaGetSymbolAddress((void**)&ff2,   g_ff2);
    cudaGetSymbolAddress((void**)&wqkvt, g_wqkvt);
    cudaGetSymbolAddress((void**)&wot,   g_wot);
    cudaGetSymbolAddress((void**)&w1t,   g_w1t);
    cudaGetSymbolAddress((void**)&w2t,   g_w2t);
    cudaGetSymbolAddress((void**)&bqkv,  g_bqkv);

    cudaFuncSetAttribute(hgemm,    cudaFuncAttributeMaxDynamicSharedMemorySize, HG_SMEM);
    cudaFuncSetAttribute(attn_f16, cudaFuncAttributeMaxDynamicSharedMemorySize, ATTN_SMEM);

    // prologue
    to_half<<<(Ms * Ds / 4 + 255) / 256, 256>>>(x, xh, Ms * Ds / 4);
    transpose_all<<<3072, dim3(32, 8)>>>(Wq, Wk, Wv, Wo, W1, W2, wqkvt, wot, w1t, w2t);
    concat3<<<3, 512>>>(bq, bk, bv, bqkv);

    // fused QKV -> half
    hgemm<<<dim3(QS / 128, Ms / 128), 256, HG_SMEM>>>(xh, wqkvt, bqkv, qkv,
                                                      Ms, QS, Ds, 0, 2);

    attn_f16<<<dim3(Ls / 64, Bb * Hh), 128, ATTN_SMEM>>>(qkv, att);

    hgemm<<<dim3(Ds / 128, Ms / 128), 256, HG_SMEM>>>(att, wot, bo, prj,
                                                      Ms, Ds, Ds, 0, 0);
    add_ln<<<Ms, 128>>>(x, prj, ln1g, ln1b, h, hr);

    hgemm<<<dim3(FFs / 128, Ms / 128), 256, HG_SMEM>>>(hr, w1t, b1, ff1,
                                                       Ms, FFs, Ds, 1, 2);
    hgemm<<<dim3(Ds / 128, Ms / 128), 256, HG_SMEM>>>(ff1, w2t, b2, ff2,
                                                      Ms, Ds, FFs, 0, 0);
    add_ln<<<Ms, 128>>>(h, ff2, ln2g, ln2b, out, nullptr);
}

// round 10
// speedup vs baseline: 1.9037x; 1.0870x over previous
#include <cuda_runtime.h>
#include <cuda_fp16.h>
#include <cstdint>

#define Bb  2
#define Ls  4096
#define Ds  512
#define Hh  8
#define HDs 64
#define FFs 2048
#define WIN 128
#define Ms  (Bb*Ls)
#define QS  1536     // fused qkv row stride (q|k|v) in halves

// ---------------- scratch (device globals: allocation-guard safe) ----------
__device__ __half g_xh  [Ms*Ds];
__device__ __half g_qkv [Ms*QS];
__device__ __half g_att [Ms*Ds];
__device__ float  g_prj [Ms*Ds];
__device__ float  g_h   [Ms*Ds];
__device__ __half g_hr  [Ms*Ds];
__device__ __half g_ff1 [Ms*FFs];
__device__ float  g_ff2 [Ms*Ds];
__device__ __half g_wqkvt[3*Ds*Ds];
__device__ __half g_wot [Ds*Ds];
__device__ __half g_w1t [Ds*FFs];
__device__ __half g_w2t [FFs*Ds];
__device__ float  g_bqkv[QS];

// ---------------- helpers ---------------------------------------------------
__device__ __forceinline__ void cp16(uint32_t dst_smem, const void* src) {
    asm volatile("cp.async.ca.shared.global [%0], [%1], 16;\n"
                 :: "r"(dst_smem), "l"(src));
}
#define CP_COMMIT() asm volatile("cp.async.commit_group;\n")
#define CP_WAIT(n)  asm volatile("cp.async.wait_group %0;\n" :: "n"(n))

__device__ __forceinline__ uint32_t f2tf(float x) {
    uint32_t u;
    asm("cvt.rna.tf32.f32 %0, %1;" : "=r"(u) : "f"(x));
    return u;
}
__device__ __forceinline__ float rna(float x) { return __uint_as_float(f2tf(x)); }

__device__ __forceinline__ void mma_f16(float d[4],
    uint32_t a0, uint32_t a1, uint32_t a2, uint32_t a3, uint32_t b0, uint32_t b1)
{
    asm volatile(
        "mma.sync.aligned.m16n8k16.row.col.f32.f16.f16.f32 "
        "{%0,%1,%2,%3}, {%4,%5,%6,%7}, {%8,%9}, {%0,%1,%2,%3};\n"
        : "+f"(d[0]), "+f"(d[1]), "+f"(d[2]), "+f"(d[3])
        : "r"(a0), "r"(a1), "r"(a2), "r"(a3), "r"(b0), "r"(b1));
}

__device__ __forceinline__ void ldsm_x4(uint32_t r[4], uint32_t addr)
{
    asm volatile("ldmatrix.sync.aligned.m8n8.x4.shared.b16 {%0,%1,%2,%3}, [%4];"
                 : "=r"(r[0]), "=r"(r[1]), "=r"(r[2]), "=r"(r[3]) : "r"(addr));
}
__device__ __forceinline__ void ldsm_x4_trans(uint32_t& r0, uint32_t& r1,
                                              uint32_t& r2, uint32_t& r3, uint32_t addr)
{
    asm volatile("ldmatrix.sync.aligned.m8n8.x4.trans.shared.b16 {%0,%1,%2,%3}, [%4];"
                 : "=r"(r0), "=r"(r1), "=r"(r2), "=r"(r3) : "r"(addr));
}

// ================= prologue kernels =========================================
__global__ __launch_bounds__(256)
void to_half(const float* __restrict__ in, __half* __restrict__ o, int n4)
{
    int i = blockIdx.x * blockDim.x + threadIdx.x;
    if (i < n4) {
        float4 t = ((const float4*)in)[i];
        __half2 lo = __floats2half2_rn(t.x, t.y);
        __half2 hi = __floats2half2_rn(t.z, t.w);
        ((uint2*)o)[i] = make_uint2(*(uint32_t*)&lo, *(uint32_t*)&hi);
    }
}

// all six W[K][N] -> Wt[N][K] (half) in one launch
__global__ __launch_bounds__(256)
void transpose_all(const float* __restrict__ Wq, const float* __restrict__ Wk,
                   const float* __restrict__ Wv, const float* __restrict__ Wo,
                   const float* __restrict__ W1, const float* __restrict__ W2,
                   __half* __restrict__ wqkvt, __half* __restrict__ wot,
                   __half* __restrict__ w1t,   __half* __restrict__ w2t)
{
    const int bid = blockIdx.x;
    const float* W; __half* Wt; int K, N, tile;
    if      (bid < 256)  { W = Wq; Wt = wqkvt;               K = Ds;  N = Ds;  tile = bid; }
    else if (bid < 512)  { W = Wk; Wt = wqkvt + Ds * Ds;     K = Ds;  N = Ds;  tile = bid - 256; }
    else if (bid < 768)  { W = Wv; Wt = wqkvt + 2 * Ds * Ds; K = Ds;  N = Ds;  tile = bid - 512; }
    else if (bid < 1024) { W = Wo; Wt = wot;                 K = Ds;  N = Ds;  tile = bid - 768; }
    else if (bid < 2048) { W = W1; Wt = w1t;                 K = Ds;  N = FFs; tile = bid - 1024; }
    else                 { W = W2; Wt = w2t;                 K = FFs; N = Ds;  tile = bid - 2048; }
    const int ntx = N / 32;
    const int nx = (tile % ntx) * 32, ky = (tile / ntx) * 32;

    __shared__ float t[32][33];
    const int x = threadIdx.x, y = threadIdx.y;
#pragma unroll
    for (int j = 0; j < 32; j += 8)
        t[y + j][x] = W[(size_t)(ky + y + j) * N + nx + x];
    __syncthreads();
#pragma unroll
    for (int j = 0; j < 32; j += 8)
        Wt[(size_t)(nx + y + j) * K + ky + x] = __float2half(t[x][y + j]);
}

__global__ void concat3(const float* __restrict__ a, const float* __restrict__ b,
                        const float* __restrict__ c, float* __restrict__ o)
{
    int i = blockIdx.x * blockDim.x + threadIdx.x;
    o[i] = (i < Ds) ? a[i] : (i < 2 * Ds) ? b[i - Ds] : c[i - 2 * Ds];
}

// ================= fp16 tensor-core GEMM ====================================
// C[M,N] = A[M,K] @ Bt[N,K]^T + bias.
// 256 thr, CTA tile 128x256x64, warp grid 2x4, warp tile 64x64 (fat tiles to
// cut smem crossbar bytes/FLOP). 3-stage cp.async pipeline, ldmatrix loads.
// out_mode: 0 = fp32, 1 = fp32 rna-rounded, 2 = half
#define HST    72
#define HAS    (128 * HST)                 // halves in A stage
#define HBS    (256 * HST)                 // halves in B stage
#define HSTG   (HAS + HBS)                 // halves per stage
#define HG_SMEM (3 * HSTG * 2)             // 3 stages (bytes)

__global__ __launch_bounds__(256, 1)
void hgemm(const __half* __restrict__ A, const __half* __restrict__ Bt,
           const float* __restrict__ bias, void* __restrict__ Cv,
           int M, int N, int K, int relu, int out_mode)
{
    extern __shared__ __align__(256) __half sh[];
    const uint32_t sb = (uint32_t)__cvta_generic_to_shared(sh);

    const int tid  = threadIdx.x;
    const int lane = tid & 31;
    const int warp = tid >> 5;
    const int gid  = lane >> 2;
    const int tg   = lane & 3;
    const int wm   = (warp >> 2) * 64;      // 0 / 64
    const int wn   = (warp & 3) * 64;       // 0..192
    const int bm   = blockIdx.y * 128;
    const int bn   = blockIdx.x * 256;

    const int ar = tid >> 3;                // 0..31
    const int ac = (tid & 7) * 8;           // half offset (16B)

    // ldmatrix lane offsets
    const int a_row = wm + ((lane >> 3) & 1) * 8 + (lane & 7);   // + im*16
    const int a_k   = ((lane >> 4) & 1) * 8;                     // + kk
    const int b_row = wn + ((lane >> 4) & 1) * 8 + (lane & 7);   // + jp*16
    const int b_k   = ((lane >> 3) & 1) * 8;                     // + kk

    float d[4][8][4];
#pragma unroll
    for (int i = 0; i < 4; i++)
#pragma unroll
        for (int j = 0; j < 8; j++)
#pragma unroll
            for (int c = 0; c < 4; c++) d[i][j][c] = 0.f;

    auto do_load = [&](int stage, int k0) {
        const __half* pa = A  + (size_t)(bm + ar) * K + k0 + ac;
        const __half* pb = Bt + (size_t)(bn + ar) * K + k0 + ac;
        const uint32_t ba = sb + (uint32_t)stage * (HSTG * 2);
        const uint32_t bb = ba + HAS * 2;
#pragma unroll
        for (int i = 0; i < 4; i++) {
            uint32_t off = (uint32_t)((ar + 32 * i) * HST + ac) * 2;
            cp16(ba + off, pa + (size_t)32 * i * K);
        }
#pragma unroll
        for (int i = 0; i < 8; i++) {
            uint32_t off = (uint32_t)((ar + 32 * i) * HST + ac) * 2;
            cp16(bb + off, pb + (size_t)32 * i * K);
        }
    };

    const int T = K / 64;
    do_load(0, 0);
    CP_COMMIT();
    if (T > 1) { do_load(1, 64); CP_COMMIT(); }

    for (int t = 0; t < T; t++) {
        if (t + 1 < T) { CP_WAIT(1); } else { CP_WAIT(0); }
        __syncthreads();

        const int buf = t % 3;
        const uint32_t sA = sb + (uint32_t)buf * (HSTG * 2);
        const uint32_t sB = sA + HAS * 2;

#pragma unroll
        for (int kk = 0; kk < 64; kk += 16) {
            uint32_t af[4][4], bf[4][4];
#pragma unroll
            for (int im = 0; im < 4; im++)
                ldsm_x4(af[im], sA + (uint32_t)((a_row + im * 16) * HST + kk + a_k) * 2);
#pragma unroll
            for (int jp = 0; jp < 4; jp++)
                ldsm_x4(bf[jp], sB + (uint32_t)((b_row + jp * 16) * HST + kk + b_k) * 2);
#pragma unroll
            for (int im = 0; im < 4; im++)
#pragma unroll
                for (int jn = 0; jn < 8; jn++)
                    mma_f16(d[im][jn], af[im][0], af[im][1], af[im][2], af[im][3],
                            bf[jn >> 1][(jn & 1) * 2], bf[jn >> 1][(jn & 1) * 2 + 1]);
        }

        if (t + 2 < T) { do_load((t + 2) % 3, (t + 2) * 64); CP_COMMIT(); }
    }

    // epilogue
#pragma unroll
    for (int jn = 0; jn < 8; jn++) {
        const int col = bn + wn + jn * 8 + 2 * tg;
        float2 bv = *(const float2*)&bias[col];
#pragma unroll
        for (int im = 0; im < 4; im++) {
            const int row = bm + wm + im * 16 + gid;
            float v0 = d[im][jn][0] + bv.x, v1 = d[im][jn][1] + bv.y;
            float v2 = d[im][jn][2] + bv.x, v3 = d[im][jn][3] + bv.y;
            if (relu) {
                v0 = fmaxf(v0, 0.f); v1 = fmaxf(v1, 0.f);
                v2 = fmaxf(v2, 0.f); v3 = fmaxf(v3, 0.f);
            }
            if (out_mode == 2) {
                __half* Ch = (__half*)Cv;
                *(__half2*)&Ch[(size_t)row       * N + col] = __floats2half2_rn(v0, v1);
                *(__half2*)&Ch[(size_t)(row + 8) * N + col] = __floats2half2_rn(v2, v3);
            } else {
                if (out_mode == 1) { v0 = rna(v0); v1 = rna(v1); v2 = rna(v2); v3 = rna(v3); }
                float* Cf = (float*)Cv;
                *(float2*)&Cf[(size_t)row       * N + col] = make_float2(v0, v1);
                *(float2*)&Cf[(size_t)(row + 8) * N + col] = make_float2(v2, v3);
            }
        }
    }
}

// ============== banded attention, full fp16 m16n8k16 ========================
#define AST 72
#define ATTN_SMEM (3 * 64 * AST * 2)

__global__ __launch_bounds__(128)
void attn_f16(const __half* __restrict__ qkv, __half* __restrict__ out)
{
    extern __shared__ __half smh[];
    __half (*Qs)[AST] = (__half(*)[AST])smh;                 // also Ps
    __half (*Ks)[AST] = (__half(*)[AST])(smh + 64 * AST);
    const uint32_t sbase = (uint32_t)__cvta_generic_to_shared(smh);
    const uint32_t sbK = sbase + 64 * AST * 2;
    const uint32_t sbV = sbase + 2 * 64 * AST * 2;

    const int bh   = blockIdx.y;
    const int b    = bh >> 3;
    const int h    = bh & 7;
    const int q0   = blockIdx.x * 64;
    const int tid  = threadIdx.x;
    const int lane = tid & 31;
    const int warp = tid >> 5;
    const int gid  = lane >> 2;
    const int tg   = lane & 3;
    const int wm   = warp * 16;

    const int sr = tid >> 3;
    const int sc = (tid & 7) * 8;

    {
        const __half* gq = qkv + ((size_t)(b * Ls + q0 + sr)) * QS + h * HDs + sc;
        const uint32_t dq = sbase + (uint32_t)(sr * AST + sc) * 2;
#pragma unroll
        for (int i = 0; i < 4; i++)
            cp16(dq + i * (16 * AST * 2), gq + (size_t)16 * i * QS);
    }
    CP_COMMIT();
    CP_WAIT(0);
    __syncthreads();

    uint32_t qa[4][4];
#pragma unroll
    for (int kc = 0; kc < 4; kc++) {
        const __half* p0 = &Qs[wm + gid    ][kc * 16 + 2 * tg];
        const __half* p1 = &Qs[wm + gid + 8][kc * 16 + 2 * tg];
        qa[kc][0] = *(const uint32_t*)p0;
        qa[kc][1] = *(const uint32_t*)p1;
        qa[kc][2] = *(const uint32_t*)(p0 + 8);
        qa[kc][3] = *(const uint32_t*)(p1 + 8);
    }

    float o[8][4];
#pragma unroll
    for (int jn = 0; jn < 8; jn++)
#pragma unroll
        for (int c = 0; c < 4; c++) o[jn][c] = 0.f;
    float m0 = -1e30f, m1 = -1e30f, l0 = 0.f, l1 = 0.f;

    const int row0 = q0 + wm + gid;
    const int row1 = row0 + 8;
    const int kstart = max(0, q0 - WIN);
    const int kend   = min(Ls, q0 + 64 + WIN);

    const int vkey = ((lane >> 3) & 1) * 8 + (lane & 7);
    const int vdim = ((lane >> 4) & 1) * 8;

    for (int kt = kstart; kt < kend; kt += 64) {
        __syncthreads();
        {
            const __half* gk = qkv + ((size_t)(b * Ls + kt + sr)) * QS + Ds     + h * HDs + sc;
            const __half* gv = qkv + ((size_t)(b * Ls + kt + sr)) * QS + 2 * Ds + h * HDs + sc;
            const uint32_t dk = sbK + (uint32_t)(sr * AST + sc) * 2;
            const uint32_t dv = sbV + (uint32_t)(sr * AST + sc) * 2;
#pragma unroll
            for (int i = 0; i < 4; i++) {
                cp16(dk + i * (16 * AST * 2), gk + (size_t)16 * i * QS);
                cp16(dv + i * (16 * AST * 2), gv + (size_t)16 * i * QS);
            }
        }
        CP_COMMIT();
        CP_WAIT(0);
        __syncthreads();

        float s[8][4];
#pragma unroll
        for (int jn = 0; jn < 8; jn++)
#pragma unroll
            for (int c = 0; c < 4; c++) s[jn][c] = 0.f;

#pragma unroll
        for (int kc = 0; kc < 4; kc++) {
#pragma unroll
            for (int jn = 0; jn < 8; jn++) {
                const __half* bp = &Ks[jn * 8 + gid][kc * 16 + 2 * tg];
                uint32_t b0 = *(const uint32_t*)bp;
                uint32_t b1 = *(const uint32_t*)(bp + 8);
                mma_f16(s[jn], qa[kc][0], qa[kc][1], qa[kc][2], qa[kc][3], b0, b1);
            }
        }

        float rmax0 = -1e30f, rmax1 = -1e30f;
#pragma unroll
        for (int jn = 0; jn < 8; jn++) {
            int cb = kt + jn * 8 + 2 * tg;
            s[jn][0] = (abs(cb     - row0) <= WIN) ? s[jn][0] * 0.125f : -1e30f;
            s[jn][1] = (abs(cb + 1 - row0) <= WIN) ? s[jn][1] * 0.125f : -1e30f;
            s[jn][2] = (abs(cb     - row1) <= WIN) ? s[jn][2] * 0.125f : -1e30f;
            s[jn][3] = (abs(cb + 1 - row1) <= WIN) ? s[jn][3] * 0.125f : -1e30f;
            rmax0 = fmaxf(rmax0, fmaxf(s[jn][0], s[jn][1]));
            rmax1 = fmaxf(rmax1, fmaxf(s[jn][2], s[jn][3]));
        }
        rmax0 = fmaxf(rmax0, __shfl_xor_sync(0xffffffffu, rmax0, 1));
        rmax0 = fmaxf(rmax0, __shfl_xor_sync(0xffffffffu, rmax0, 2));
        rmax1 = fmaxf(rmax1, __shfl_xor_sync(0xffffffffu, rmax1, 1));
        rmax1 = fmaxf(rmax1, __shfl_xor_sync(0xffffffffu, rmax1, 2));

        float mn0 = fmaxf(m0, rmax0);
        float mn1 = fmaxf(m1, rmax1);
        float sc0 = __expf(m0 - mn0);
        float sc1 = __expf(m1 - mn1);
        m0 = mn0; m1 = mn1;
        l0 *= sc0; l1 *= sc1;
#pragma unroll
        for (int jn = 0; jn < 8; jn++) {
            o[jn][0] *= sc0; o[jn][1] *= sc0;
            o[jn][2] *= sc1; o[jn][3] *= sc1;
        }

#pragma unroll
        for (int jn = 0; jn < 8; jn++) {
            float p0 = __expf(s[jn][0] - m0);
            float p1 = __expf(s[jn][1] - m0);
            float p2 = __expf(s[jn][2] - m1);
            float p3 = __expf(s[jn][3] - m1);
            l0 += p0 + p1;
            l1 += p2 + p3;
            *(__half2*)&Qs[wm + gid    ][jn * 8 + 2 * tg] = __floats2half2_rn(p0, p1);
            *(__half2*)&Qs[wm + gid + 8][jn * 8 + 2 * tg] = __floats2half2_rn(p2, p3);
        }
        __syncwarp();

#pragma unroll
        for (int kc = 0; kc < 4; kc++) {
            const __half* pp0 = &Qs[wm + gid    ][kc * 16 + 2 * tg];
            const __half* pp1 = &Qs[wm + gid + 8][kc * 16 + 2 * tg];
            uint32_t a0 = *(const uint32_t*)pp0;
            uint32_t a1 = *(const uint32_t*)pp1;
            uint32_t a2 = *(const uint32_t*)(pp0 + 8);
            uint32_t a3 = *(const uint32_t*)(pp1 + 8);
#pragma unroll
            for (int jp = 0; jp < 4; jp++) {
                uint32_t vaddr = sbV + (uint32_t)((kc * 16 + vkey) * AST + jp * 16 + vdim) * 2;
                uint32_t b0, b1, b2, b3;
                ldsm_x4_trans(b0, b1, b2, b3, vaddr);
                mma_f16(o[jp * 2    ], a0, a1, a2, a3, b0, b1);
                mma_f16(o[jp * 2 + 1], a0, a1, a2, a3, b2, b3);
            }
        }
    }

    l0 += __shfl_xor_sync(0xffffffffu, l0, 1);
    l0 += __shfl_xor_sync(0xffffffffu, l0, 2);
    l1 += __shfl_xor_sync(0xffffffffu, l1, 1);
    l1 += __shfl_xor_sync(0xffffffffu, l1, 2);
    const float inv0 = 1.f / l0;
    const float inv1 = 1.f / l1;

    __half* o0 = out + ((size_t)(b * Ls + row0)) * Ds + h * HDs;
    __half* o1 = out + ((size_t)(b * Ls + row1)) * Ds + h * HDs;
#pragma unroll
    for (int jn = 0; jn < 8; jn++) {
        int c = jn * 8 + 2 * tg;
        *(__half2*)&o0[c] = __floats2half2_rn(o[jn][0] * inv0, o[jn][1] * inv0);
        *(__half2*)&o1[c] = __floats2half2_rn(o[jn][2] * inv1, o[jn][3] * inv1);
    }
}

// ---------------- residual + LayerNorm (optional half twin) -----------------
__global__ __launch_bounds__(128)
void add_ln(const float* __restrict__ x, const float* __restrict__ r,
            const float* __restrict__ g, const float* __restrict__ bta,
            float* __restrict__ out, __half* __restrict__ out_r)
{
    const int row = blockIdx.x;
    const int tid = threadIdx.x;
    const float* xr = x + (size_t)row * Ds;
    const float* rr = r + (size_t)row * Ds;

    __shared__ float t[Ds];
    __shared__ float s1[4], s2[4];

    float s = 0.f, ss = 0.f;
#pragma unroll
    for (int i = 0; i < 4; i++) {
        int c = tid + i * 128;
        float u = xr[c] + rr[c];
        t[c] = u;
        s += u;
        ss = fmaf(u, u, ss);
    }
#pragma unroll
    for (int o = 16; o; o >>= 1) {
        s  += __shfl_xor_sync(0xffffffffu, s,  o);
        ss += __shfl_xor_sync(0xffffffffu, ss, o);
    }
    if ((tid & 31) == 0) { s1[tid >> 5] = s; s2[tid >> 5] = ss; }
    __syncthreads();
    float S  = s1[0] + s1[1] + s1[2] + s1[3];
    float SS = s2[0] + s2[1] + s2[2] + s2[3];
    float mu   = S * (1.f / Ds);
    float var  = SS * (1.f / Ds) - mu * mu;
    float rstd = rsqrtf(var + 1e-5f);
#pragma unroll
    for (int i = 0; i < 4; i++) {
        int c = tid + i * 128;
        float val = (t[c] - mu) * rstd * g[c] + bta[c];
        out[(size_t)row * Ds + c] = val;
        if (out_r) out_r[(size_t)row * Ds + c] = __float2half(val);
    }
}

// ---------------- launch ----------------------------------------------------
extern "C" void kernel_launch(void* const* d_in, const int* in_sizes, int n_in,
                              void* d_out, int out_size)
{
    const float* x    = (const float*)d_in[0];
    const float* Wq   = (const float*)d_in[1];
    const float* bq   = (const float*)d_in[2];
    const float* Wk   = (const float*)d_in[3];
    const float* bk   = (const float*)d_in[4];
    const float* Wv   = (const float*)d_in[5];
    const float* bv   = (const float*)d_in[6];
    const float* Wo   = (const float*)d_in[7];
    const float* bo   = (const float*)d_in[8];
    const float* ln1g = (const float*)d_in[9];
    const float* ln1b = (const float*)d_in[10];
    const float* W1   = (const float*)d_in[11];
    const float* b1   = (const float*)d_in[12];
    const float* W2   = (const float*)d_in[13];
    const float* b2   = (const float*)d_in[14];
    const float* ln2g = (const float*)d_in[15];
    const float* ln2b = (const float*)d_in[16];
    float* out = (float*)d_out;

    __half *xh, *qkv, *att, *hr, *ff1, *wqkvt, *wot, *w1t, *w2t;
    float  *prj, *h, *ff2, *bqkv;
    cudaGetSymbolAddress((void**)&xh,    g_xh);
    cudaGetSymbolAddress((void**)&qkv,   g_qkv);
    cudaGetSymbolAddress((void**)&att,   g_att);
    cudaGetSymbolAddress((void**)&prj,   g_prj);
    cudaGetSymbolAddress((void**)&h,     g_h);
    cudaGetSymbolAddress((void**)&hr,    g_hr);
    cudaGetSymbolAddress((void**)&ff1,   g_ff1);
    cudaGetSymbolAddress((void**)&ff2,   g_ff2);
    cudaGetSymbolAddress((void**)&wqkvt, g_wqkvt);
    cudaGetSymbolAddress((void**)&wot,   g_wot);
    cudaGetSymbolAddress((void**)&w1t,   g_w1t);
    cudaGetSymbolAddress((void**)&w2t,   g_w2t);
    cudaGetSymbolAddress((void**)&bqkv,  g_bqkv);

    cudaFuncSetAttribute(hgemm,    cudaFuncAttributeMaxDynamicSharedMemorySize, HG_SMEM);
    cudaFuncSetAttribute(attn_f16, cudaFuncAttributeMaxDynamicSharedMemorySize, ATTN_SMEM);

    // prologue
    to_half<<<(Ms * Ds / 4 + 255) / 256, 256>>>(x, xh, Ms * Ds / 4);
    transpose_all<<<3072, dim3(32, 8)>>>(Wq, Wk, Wv, Wo, W1, W2, wqkvt, wot, w1t, w2t);
    concat3<<<3, 512>>>(bq, bk, bv, bqkv);

    // fused QKV -> half
    hgemm<<<dim3(QS / 256, Ms / 128), 256, HG_SMEM>>>(xh, wqkvt, bqkv, qkv,
                                                      Ms, QS, Ds, 0, 2);

    attn_f16<<<dim3(Ls / 64, Bb * Hh), 128, ATTN_SMEM>>>(qkv, att);

    hgemm<<<dim3(Ds / 256, Ms / 128), 256, HG_SMEM>>>(att, wot, bo, prj,
                                                      Ms, Ds, Ds, 0, 0);
    add_ln<<<Ms, 128>>>(x, prj, ln1g, ln1b, h, hr);

    hgemm<<<dim3(FFs / 256, Ms / 128), 256, HG_SMEM>>>(hr, w1t, b1, ff1,
                                                       Ms, FFs, Ds, 1, 2);
    hgemm<<<dim3(Ds / 256, Ms / 128), 256, HG_SMEM>>>(ff1, w2t, b2, ff2,
                                                      Ms, Ds, FFs, 0, 0);
    add_ln<<<Ms, 128>>>(h, ff2, ln2g, ln2b, out, nullptr);
}